// round 4
// baseline (speedup 1.0000x reference)
#include <cuda_runtime.h>
#include <cstdint>

// ---------------- problem constants (fixed shapes from reference) ----------------
constexpr int MODAL  = 8;      // M (sequence / modal length)
constexpr int DMODEL = 1024;   // d_model
constexpr int NHEAD  = 16;
constexpr int DK     = 64;
constexpr int SEXT   = 64;     // external attention S
constexpr int BSZ    = 4096;
constexpr int ROWS   = BSZ * MODAL;   // 32768

// ---------------- scratch (device globals: allocation-free) ----------------
__device__ float g_q  [(size_t)ROWS * DMODEL];
__device__ float g_k  [(size_t)ROWS * DMODEL];
__device__ float g_v  [(size_t)ROWS * DMODEL];
__device__ float g_att[(size_t)ROWS * DMODEL];   // attn out (tf32-rounded), later x (tf32-rounded)
__device__ float g_x  [(size_t)ROWS * DMODEL];
__device__ float g_scores[(size_t)BSZ * NHEAD * MODAL * MODAL];
__device__ float g_xa [(size_t)ROWS * SEXT];
__device__ float g_a  [(size_t)ROWS * SEXT];
// tf32-rounded weights
__device__ float g_wq [(size_t)DMODEL * DMODEL];
__device__ float g_wk [(size_t)DMODEL * DMODEL];
__device__ float g_wv [(size_t)DMODEL * DMODEL];
__device__ float g_wfc[(size_t)DMODEL * DMODEL];
__device__ float g_wmk[(size_t)SEXT * DMODEL];
__device__ float g_wmv[(size_t)DMODEL * SEXT];
__device__ unsigned g_min_u;

// ---------------- float<->orderable-uint encoding for global atomic min ----------------
__device__ __forceinline__ unsigned enc_min(float f) {
    unsigned u = __float_as_uint(f);
    return (u & 0x80000000u) ? ~u : (u | 0x80000000u);
}
__device__ __forceinline__ float dec_min(unsigned k) {
    return (k & 0x80000000u) ? __uint_as_float(k ^ 0x80000000u)
                             : __uint_as_float(~k);
}

__global__ void init_min_kernel() { g_min_u = 0xFFFFFFFFu; }

// ---------------- tf32 helpers ----------------
__device__ __forceinline__ unsigned f2tf(float f) {
    unsigned r;
    asm("cvt.rna.tf32.f32 %0, %1;" : "=r"(r) : "f"(f));
    return r;
}
__device__ __forceinline__ float f2tf_f(float f) { return __uint_as_float(f2tf(f)); }

__device__ __forceinline__ void mma_tf32(float* c, const unsigned* a, const unsigned* b) {
    asm volatile(
        "mma.sync.aligned.m16n8k8.row.col.f32.tf32.tf32.f32 "
        "{%0,%1,%2,%3}, {%4,%5,%6,%7}, {%8,%9}, {%0,%1,%2,%3};\n"
        : "+f"(c[0]), "+f"(c[1]), "+f"(c[2]), "+f"(c[3])
        : "r"(a[0]), "r"(a[1]), "r"(a[2]), "r"(a[3]),
          "r"(b[0]), "r"(b[1]));
}

__device__ __forceinline__ uint32_t smem_u32(const void* p) {
    uint32_t a;
    asm("{ .reg .u64 t; cvta.to.shared.u64 t, %1; cvt.u32.u64 %0, t; }" : "=r"(a) : "l"(p));
    return a;
}
__device__ __forceinline__ unsigned lds_u32(uint32_t a) {
    unsigned v;
    asm volatile("ld.shared.b32 %0, [%1];" : "=r"(v) : "r"(a));
    return v;
}
__device__ __forceinline__ void cp16(uint32_t dst, const void* src) {
    asm volatile("cp.async.cg.shared.global [%0], [%1], 16;" :: "r"(dst), "l"(src));
}
#define CP_COMMIT() asm volatile("cp.async.commit_group;" ::: "memory")
#define CP_WAIT2()  asm volatile("cp.async.wait_group 2;" ::: "memory")

// ---------------- weight tf32 pre-round ----------------
__global__ void cvt_kernel(const float4* __restrict__ s, float4* __restrict__ d, int n4) {
    int i = blockIdx.x * 256 + threadIdx.x;
    if (i < n4) {
        float4 v = s[i];
        d[i] = make_float4(f2tf_f(v.x), f2tf_f(v.y), f2tf_f(v.z), f2tf_f(v.w));
    }
}

// =====================================================================
// NT GEMM via cp.async + swizzled k-major smem + tf32 HMMA.
// C[M,N] = A[M,K] * B[N,K]^T (+ Res). BM=128, BK=32, BN in {128,64}.
// word(m,kk) = m*32 + (((kk>>2) ^ (m&7)) << 2) + (kk&3); loads & stores
// bank-conflict-free. Fragment addresses: register base ^ compile-time const.
// CVTA: round A fragments to tf32 on read (when A is raw fp32).
// B (and A when !CVTA) must already hold tf32 bit patterns.
// =====================================================================
template<int BN, bool RES, bool CVTA>
__global__ void __launch_bounds__(256, 2) gemm_tf(
    const float* __restrict__ A, const float* __restrict__ B,
    const float* __restrict__ Res, float* __restrict__ C, int K, int N)
{
    constexpr int AW = 128 * 32;          // words per A stage
    constexpr int BW = BN * 32;
    constexpr int STW = AW + BW;
    constexpr int BCH = BN * 8 / 256;     // B cp.async chunks per thread
    constexpr int WNT = BN / 2;
    constexpr int NT  = WNT / 8;
    constexpr int MT  = 2;

    extern __shared__ float smf[];
    const uint32_t sbase = smem_u32(smf);

    const int tid  = threadIdx.x;
    const int lane = tid & 31;
    const int wid  = tid >> 5;
    const int wm   = wid & 3;
    const int wn   = wid >> 2;
    const int bm   = blockIdx.y * 128;
    const int bn   = blockIdx.x * BN;

    const int mA = tid >> 3;
    const int cA = tid & 7;
    const int nk = K / 32;

    auto issue = [&](int kt, int s) {
        const uint32_t so = (uint32_t)s * (STW * 4u);
        const int k0 = kt * 32;
#pragma unroll
        for (int i = 0; i < 4; i++) {
            const int m = mA + 32 * i;
            const uint32_t dst = sbase + so + (uint32_t)m * 128u + (uint32_t)((cA ^ (m & 7)) << 4);
            cp16(dst, A + (size_t)(bm + m) * K + k0 + cA * 4);
        }
#pragma unroll
        for (int i = 0; i < BCH; i++) {
            const int m = mA + 32 * i;
            const uint32_t dst = sbase + so + AW * 4u
                               + (uint32_t)m * 128u + (uint32_t)((cA ^ (m & 7)) << 4);
            cp16(dst, B + (size_t)(bn + m) * K + k0 + cA * 4);
        }
    };

    float acc[MT][NT][4];
#pragma unroll
    for (int i = 0; i < MT; i++)
#pragma unroll
        for (int j = 0; j < NT; j++)
#pragma unroll
            for (int t = 0; t < 4; t++) acc[i][j][t] = 0.f;

    issue(0, 0); CP_COMMIT();
    issue(1, 1); CP_COMMIT();

    // fragment byte-offset bases (stage-local). msw == nsw == (lane>>2)&7.
    const uint32_t kkl4 = (uint32_t)(lane & 3) << 2;
    const uint32_t sw4  = (uint32_t)((lane >> 2) & 7) << 4;
    uint32_t abase[MT], bbase[NT];
#pragma unroll
    for (int i = 0; i < MT; i++) {
        const int m0 = wm * 32 + i * 16 + (lane >> 2);
        abase[i] = (uint32_t)m0 * 128u + sw4 + kkl4;
    }
#pragma unroll
    for (int j = 0; j < NT; j++) {
        const int n0 = wn * WNT + j * 8 + (lane >> 2);
        bbase[j] = (uint32_t)n0 * 128u + sw4 + kkl4;
    }

    for (int kt = 0; kt < nk; kt++) {
        const int s = kt % 3;
        if (kt + 2 < nk) issue(kt + 2, (kt + 2) % 3);
        CP_COMMIT();
        CP_WAIT2();
        __syncthreads();

        const uint32_t sa = sbase + (uint32_t)s * (STW * 4u);
        const uint32_t sb = sa + AW * 4u;

#pragma unroll
        for (int ks = 0; ks < 4; ks++) {
            const uint32_t c0 = (uint32_t)(2 * ks) << 4;       // compile-time
            const uint32_t c1 = (uint32_t)(2 * ks + 1) << 4;   // compile-time
            unsigned af[MT][4], bf[NT][2];
#pragma unroll
            for (int i = 0; i < MT; i++) {
                const uint32_t a0 = sa + (abase[i] ^ c0);
                const uint32_t a1 = sa + (abase[i] ^ c1);
                if (CVTA) {
                    af[i][0] = f2tf(__uint_as_float(lds_u32(a0)));
                    af[i][1] = f2tf(__uint_as_float(lds_u32(a0 + 1024u)));
                    af[i][2] = f2tf(__uint_as_float(lds_u32(a1)));
                    af[i][3] = f2tf(__uint_as_float(lds_u32(a1 + 1024u)));
                } else {
                    af[i][0] = lds_u32(a0);
                    af[i][1] = lds_u32(a0 + 1024u);
                    af[i][2] = lds_u32(a1);
                    af[i][3] = lds_u32(a1 + 1024u);
                }
            }
#pragma unroll
            for (int j = 0; j < NT; j++) {
                bf[j][0] = lds_u32(sb + (bbase[j] ^ c0));
                bf[j][1] = lds_u32(sb + (bbase[j] ^ c1));
            }
#pragma unroll
            for (int i = 0; i < MT; i++)
#pragma unroll
                for (int j = 0; j < NT; j++)
                    mma_tf32(acc[i][j], af[i], bf[j]);
        }
        __syncthreads();
    }

    // epilogue
#pragma unroll
    for (int i = 0; i < MT; i++) {
#pragma unroll
        for (int j = 0; j < NT; j++) {
            const int r0 = bm + wm * 32 + i * 16 + (lane >> 2);
            const int c0 = bn + wn * WNT + j * 8 + (lane & 3) * 2;
            float2 v0 = make_float2(acc[i][j][0], acc[i][j][1]);
            float2 v1 = make_float2(acc[i][j][2], acc[i][j][3]);
            if (RES) {
                float2 ra = *(const float2*)&Res[(size_t)r0 * N + c0];
                float2 rb = *(const float2*)&Res[(size_t)(r0 + 8) * N + c0];
                v0.x += ra.x; v0.y += ra.y;
                v1.x += rb.x; v1.y += rb.y;
            }
            *(float2*)&C[(size_t)r0 * N + c0] = v0;
            *(float2*)&C[(size_t)(r0 + 8) * N + c0] = v1;
        }
    }
}

// ---------------- attention pass A: scores + global min ----------------
constexpr int QPAD = DMODEL + 4;

extern __shared__ float dynsmem[];

__global__ void __launch_bounds__(256) attn_scores_kernel() {
    float* qs = dynsmem;
    float* ks = dynsmem + MODAL * QPAD;
    const int b = blockIdx.x, tid = threadIdx.x;
    const float4* qg = (const float4*)(g_q + (size_t)b * MODAL * DMODEL);
    const float4* kg = (const float4*)(g_k + (size_t)b * MODAL * DMODEL);
    for (int i = tid; i < MODAL * DMODEL / 4; i += 256) {
        int m = i >> 8, c = i & 255;
        *(float4*)&qs[m * QPAD + c * 4] = qg[i];
        *(float4*)&ks[m * QPAD + c * 4] = kg[i];
    }
    __syncthreads();

    float lmin = 3.4e38f;
    for (int s = tid; s < NHEAD * MODAL * MODAL; s += 256) {
        int h = s >> 6, m = (s >> 3) & 7, n = s & 7;
        const float4* qr = (const float4*)&qs[m * QPAD + h * DK];
        const float4* kr = (const float4*)&ks[n * QPAD + h * DK];
        float acc = 0.f;
#pragma unroll
        for (int d = 0; d < 16; d++) {
            float4 a = qr[d], c = kr[d];
            acc += a.x * c.x + a.y * c.y + a.z * c.z + a.w * c.w;
        }
        acc *= 0.125f;
        g_scores[(size_t)b * 1024 + s] = acc;
        lmin = fminf(lmin, acc);
    }
#pragma unroll
    for (int o = 16; o; o >>= 1) lmin = fminf(lmin, __shfl_xor_sync(0xffffffffu, lmin, o));
    __shared__ float wmn[8];
    if ((tid & 31) == 0) wmn[tid >> 5] = lmin;
    __syncthreads();
    if (tid == 0) {
        float m = wmn[0];
#pragma unroll
        for (int i = 1; i < 8; i++) m = fminf(m, wmn[i]);
        atomicMin(&g_min_u, enc_min(m));
    }
}

// ---------------- attention pass B (writes tf32-rounded attn output) ----------------
__global__ void __launch_bounds__(256) attn_out_kernel() {
    __shared__ float vs[MODAL * QPAD];
    __shared__ float sc[NHEAD * 64];
    __shared__ float aw[NHEAD * 64];
    const int b = blockIdx.x, tid = threadIdx.x;
    const float inv = 1.f / fabsf(dec_min(g_min_u));

    const float4* vg = (const float4*)(g_v + (size_t)b * MODAL * DMODEL);
    for (int i = tid; i < MODAL * DMODEL / 4; i += 256) {
        int m = i >> 8, c = i & 255;
        *(float4*)&vs[m * QPAD + c * 4] = vg[i];
    }
    for (int i = tid; i < 1024; i += 256)
        sc[i] = g_scores[(size_t)b * 1024 + i] * inv;
    __syncthreads();

    if (tid < 128) {
        int h = tid >> 3, m = tid & 7;
        float r[8]; float ss = 0.f;
#pragma unroll
        for (int n = 0; n < 8; n++) { r[n] = sc[h * 64 + m * 8 + n]; ss += r[n] * r[n]; }
        float nrm = fmaxf(sqrtf(ss), 1e-12f);
        float rn = 1.f / nrm;
        float mx = -3.4e38f;
#pragma unroll
        for (int n = 0; n < 8; n++) { r[n] *= rn; mx = fmaxf(mx, r[n]); }
        float sum = 0.f;
#pragma unroll
        for (int n = 0; n < 8; n++) { r[n] = expf(r[n] - mx); sum += r[n]; }
        float is = 1.f / sum;
#pragma unroll
        for (int n = 0; n < 8; n++) aw[h * 64 + m * 8 + n] = r[n] * is;
    }
    __syncthreads();

    float* og = g_att + (size_t)b * MODAL * DMODEL;
    for (int o = tid; o < MODAL * DMODEL; o += 256) {
        int m = o >> 10, col = o & 1023, h = col >> 6;
        float acc = 0.f;
#pragma unroll
        for (int n = 0; n < 8; n++) acc += aw[h * 64 + m * 8 + n] * vs[n * QPAD + col];
        og[o] = f2tf_f(acc);   // pre-rounded for the FC GEMM (no cvt on read)
    }
}

// ---------------- LayerNorm (writes exact x -> out, tf32 x -> xt) ----------------
__global__ void __launch_bounds__(256) ln_kernel(
    const float* __restrict__ gamma, const float* __restrict__ beta,
    float* __restrict__ out, float* __restrict__ xt)
{
    const int wid = threadIdx.x >> 5, lane = threadIdx.x & 31;
    const size_t row = (size_t)blockIdx.x * 8 + wid;
    const float4* xr = (const float4*)(g_x + row * DMODEL);
    float4 v[8];
    float s = 0.f, s2 = 0.f;
#pragma unroll
    for (int i = 0; i < 8; i++) {
        v[i] = xr[lane + 32 * i];
        s += v[i].x + v[i].y + v[i].z + v[i].w;
        s2 += v[i].x * v[i].x + v[i].y * v[i].y + v[i].z * v[i].z + v[i].w * v[i].w;
    }
#pragma unroll
    for (int o = 16; o; o >>= 1) {
        s += __shfl_xor_sync(0xffffffffu, s, o);
        s2 += __shfl_xor_sync(0xffffffffu, s2, o);
    }
    const float mu = s * (1.f / DMODEL);
    const float var = fmaxf(s2 * (1.f / DMODEL) - mu * mu, 0.f);
    const float rs = rsqrtf(var + 1e-10f);
    float4* orow = (float4*)(out + row * DMODEL);
    float4* trow = (float4*)(xt + row * DMODEL);
    const float4* gm = (const float4*)gamma;
    const float4* bt = (const float4*)beta;
#pragma unroll
    for (int i = 0; i < 8; i++) {
        int c4 = lane + 32 * i;
        float4 g = gm[c4], bb = bt[c4], x = v[i], r;
        r.x = (x.x - mu) * rs * g.x + bb.x;
        r.y = (x.y - mu) * rs * g.y + bb.y;
        r.z = (x.z - mu) * rs * g.z + bb.z;
        r.w = (x.w - mu) * rs * g.w + bb.w;
        orow[c4] = r;
        trow[c4] = make_float4(f2tf_f(r.x), f2tf_f(r.y), f2tf_f(r.z), f2tf_f(r.w));
    }
}

// ---------------- ExternalAttention normalization (writes tf32-rounded a) ----------------
__global__ void __launch_bounds__(64) ext_norm_kernel() {
    const int b = blockIdx.x, s = threadIdx.x;
    __shared__ float sm[MODAL][SEXT];
    __shared__ float rsum[MODAL];
    float xv[MODAL];
    float mx = -3.4e38f;
#pragma unroll
    for (int m = 0; m < MODAL; m++) {
        xv[m] = g_xa[((size_t)b * MODAL + m) * SEXT + s];
        mx = fmaxf(mx, xv[m]);
    }
    float sum = 0.f;
#pragma unroll
    for (int m = 0; m < MODAL; m++) { xv[m] = expf(xv[m] - mx); sum += xv[m]; }
    const float is = 1.f / sum;
#pragma unroll
    for (int m = 0; m < MODAL; m++) sm[m][s] = xv[m] * is;
    __syncthreads();
    if (s < MODAL) {
        float t = 0.f;
        for (int j = 0; j < SEXT; j++) t += sm[s][j];
        rsum[s] = 1.f / t;
    }
    __syncthreads();
#pragma unroll
    for (int m = 0; m < MODAL; m++)
        g_a[((size_t)b * MODAL + m) * SEXT + s] = f2tf_f(sm[m][s] * rsum[m]);
}

// ---------------- launch ----------------
extern "C" void kernel_launch(void* const* d_in, const int* in_sizes, int n_in,
                              void* d_out, int out_size)
{
    const float* q     = (const float*)d_in[0];
    const float* k     = (const float*)d_in[1];
    const float* v     = (const float*)d_in[2];
    const float* Wq    = (const float*)d_in[3];
    const float* Wk    = (const float*)d_in[4];
    const float* Wv    = (const float*)d_in[5];
    const float* Wfc   = (const float*)d_in[6];
    const float* gamma = (const float*)d_in[7];
    const float* beta  = (const float*)d_in[8];
    const float* Wmk   = (const float*)d_in[9];
    const float* Wmv   = (const float*)d_in[10];
    float* out = (float*)d_out;

    float *pq, *pk, *pv, *patt, *px, *pxa, *pa;
    float *pwq, *pwk, *pwv, *pwfc, *pwmk, *pwmv;
    cudaGetSymbolAddress((void**)&pq,   g_q);
    cudaGetSymbolAddress((void**)&pk,   g_k);
    cudaGetSymbolAddress((void**)&pv,   g_v);
    cudaGetSymbolAddress((void**)&patt, g_att);
    cudaGetSymbolAddress((void**)&px,   g_x);
    cudaGetSymbolAddress((void**)&pxa,  g_xa);
    cudaGetSymbolAddress((void**)&pa,   g_a);
    cudaGetSymbolAddress((void**)&pwq,  g_wq);
    cudaGetSymbolAddress((void**)&pwk,  g_wk);
    cudaGetSymbolAddress((void**)&pwv,  g_wv);
    cudaGetSymbolAddress((void**)&pwfc, g_wfc);
    cudaGetSymbolAddress((void**)&pwmk, g_wmk);
    cudaGetSymbolAddress((void**)&pwmv, g_wmv);

    const int smem_sc = 2 * MODAL * QPAD * (int)sizeof(float);
    cudaFuncSetAttribute(attn_scores_kernel,
                         cudaFuncAttributeMaxDynamicSharedMemorySize, smem_sc);

    const int smem128 = 3 * (128 * 32 + 128 * 32) * (int)sizeof(float);  // 98304
    const int smem64  = 3 * (128 * 32 + 64 * 32) * (int)sizeof(float);   // 73728
    cudaFuncSetAttribute(gemm_tf<128, false, true>,
                         cudaFuncAttributeMaxDynamicSharedMemorySize, smem128);
    cudaFuncSetAttribute(gemm_tf<128, true, false>,
                         cudaFuncAttributeMaxDynamicSharedMemorySize, smem128);
    cudaFuncSetAttribute(gemm_tf<64, false, false>,
                         cudaFuncAttributeMaxDynamicSharedMemorySize, smem64);

    init_min_kernel<<<1, 1>>>();

    // weight tf32 pre-round (33 MB total)
    const int w4 = DMODEL * DMODEL / 4;           // 262144
    const int s4 = SEXT * DMODEL / 4;             // 16384
    cvt_kernel<<<(w4 + 255) / 256, 256>>>((const float4*)Wq,  (float4*)pwq,  w4);
    cvt_kernel<<<(w4 + 255) / 256, 256>>>((const float4*)Wk,  (float4*)pwk,  w4);
    cvt_kernel<<<(w4 + 255) / 256, 256>>>((const float4*)Wv,  (float4*)pwv,  w4);
    cvt_kernel<<<(w4 + 255) / 256, 256>>>((const float4*)Wfc, (float4*)pwfc, w4);
    cvt_kernel<<<(s4 + 255) / 256, 256>>>((const float4*)Wmk, (float4*)pwmk, s4);
    cvt_kernel<<<(s4 + 255) / 256, 256>>>((const float4*)Wmv, (float4*)pwmv, s4);

    dim3 g1(DMODEL / 128, ROWS / 128);  // (8, 256)
    gemm_tf<128, false, true><<<g1, 256, smem128>>>(q, pwq, nullptr, pq, DMODEL, DMODEL);
    gemm_tf<128, false, true><<<g1, 256, smem128>>>(k, pwk, nullptr, pk, DMODEL, DMODEL);
    gemm_tf<128, false, true><<<g1, 256, smem128>>>(v, pwv, nullptr, pv, DMODEL, DMODEL);

    attn_scores_kernel<<<BSZ, 256, smem_sc>>>();
    attn_out_kernel<<<BSZ, 256>>>();

    // x = attn_out @ Wfc^T + q (residual); A pre-rounded -> no cvt
    gemm_tf<128, true, false><<<g1, 256, smem128>>>(patt, pwfc, q, px, DMODEL, DMODEL);

    // LayerNorm -> d_out (exact) + g_att (tf32 copy of x)
    ln_kernel<<<ROWS / 8, 256>>>(gamma, beta, out, patt);

    // xa = x @ Wmk^T  (N=64); A = tf32 x
    gemm_tf<64, false, false><<<dim3(1, ROWS / 128), 256, smem64>>>(patt, pwmk, nullptr, pxa,
                                                                    DMODEL, SEXT);
    ext_norm_kernel<<<BSZ, 64>>>();

    // out = x + a @ Wmv^T  (K=64); A = tf32 a
    gemm_tf<128, true, false><<<dim3(DMODEL / 128, ROWS / 128), 256, smem128>>>(pa, pwmv, out, out,
                                                                                SEXT, DMODEL);
}

// round 5
// speedup vs baseline: 1.0415x; 1.0415x over previous
#include <cuda_runtime.h>
#include <cstdint>

// ---------------- problem constants (fixed shapes from reference) ----------------
constexpr int MODAL  = 8;      // M (sequence / modal length)
constexpr int DMODEL = 1024;   // d_model
constexpr int NHEAD  = 16;
constexpr int DK     = 64;
constexpr int SEXT   = 64;     // external attention S
constexpr int BSZ    = 4096;
constexpr int ROWS   = BSZ * MODAL;   // 32768

// ---------------- scratch (device globals: allocation-free) ----------------
__device__ float g_q  [(size_t)ROWS * DMODEL];
__device__ float g_k  [(size_t)ROWS * DMODEL];
__device__ float g_v  [(size_t)ROWS * DMODEL];
__device__ float g_att[(size_t)ROWS * DMODEL];
__device__ float g_x  [(size_t)ROWS * DMODEL];
__device__ float g_scores[(size_t)BSZ * NHEAD * MODAL * MODAL];
__device__ float g_xa [(size_t)ROWS * SEXT];
__device__ float g_a  [(size_t)ROWS * SEXT];
__device__ unsigned g_min_u;

// ---------------- float<->orderable-uint encoding for global atomic min ----------------
__device__ __forceinline__ unsigned enc_min(float f) {
    unsigned u = __float_as_uint(f);
    return (u & 0x80000000u) ? ~u : (u | 0x80000000u);
}
__device__ __forceinline__ float dec_min(unsigned k) {
    return (k & 0x80000000u) ? __uint_as_float(k ^ 0x80000000u)
                             : __uint_as_float(~k);
}

__global__ void init_min_kernel() { g_min_u = 0xFFFFFFFFu; }

// ---------------- tf32 helpers ----------------
__device__ __forceinline__ unsigned f2tf(float f) {
    unsigned r;
    asm("cvt.rna.tf32.f32 %0, %1;" : "=r"(r) : "f"(f));
    return r;
}

__device__ __forceinline__ void mma_tf32(float* c, const unsigned* a, const unsigned* b) {
    asm volatile(
        "mma.sync.aligned.m16n8k8.row.col.f32.tf32.tf32.f32 "
        "{%0,%1,%2,%3}, {%4,%5,%6,%7}, {%8,%9}, {%0,%1,%2,%3};\n"
        : "+f"(c[0]), "+f"(c[1]), "+f"(c[2]), "+f"(c[3])
        : "r"(a[0]), "r"(a[1]), "r"(a[2]), "r"(a[3]),
          "r"(b[0]), "r"(b[1]));
}

__device__ __forceinline__ uint32_t smem_u32(const void* p) {
    uint32_t a;
    asm("{ .reg .u64 t; cvta.to.shared.u64 t, %1; cvt.u32.u64 %0, t; }" : "=r"(a) : "l"(p));
    return a;
}
__device__ __forceinline__ unsigned lds_u32(uint32_t a) {
    unsigned v;
    asm volatile("ld.shared.b32 %0, [%1];" : "=r"(v) : "r"(a));
    return v;
}
__device__ __forceinline__ void cp16(uint32_t dst, const void* src) {
    asm volatile("cp.async.cg.shared.global [%0], [%1], 16;" :: "r"(dst), "l"(src));
}
#define CP_COMMIT() asm volatile("cp.async.commit_group;" ::: "memory")
#define CP_WAIT2()  asm volatile("cp.async.wait_group 2;" ::: "memory")

// =====================================================================
// NT GEMM: cp.async + swizzled k-major smem + tf32 HMMA.
// C[M,N] = A[M,K] * B[N,K]^T (+ Res). BM=128, BK=32, BN in {128,64}.
// 128 threads = 4 warps in a 2x2 grid, 64 x (BN/2) warp tiles:
// minimizes smem->RF duplication (A 2x, B 2x) -> crossbar bytes/kt -25%.
// word(m,kk) = m*32 + (((kk>>2) ^ (m&7)) << 2) + (kk&3); all accesses
// bank-conflict-free. tf32 rounding on the read side (cvt.rna).
// =====================================================================
template<int BN, bool RES>
__global__ void __launch_bounds__(128, 2) gemm_ca(
    const float* __restrict__ A, const float* __restrict__ B,
    const float* __restrict__ Res, float* __restrict__ C, int K, int N)
{
    constexpr int AW  = 128 * 32;          // words per A stage
    constexpr int BW  = BN * 32;
    constexpr int STW = AW + BW;
    constexpr int ACH = 8;                 // A cp.async chunks per thread
    constexpr int BCH = BN * 8 / 128;      // B chunks per thread (8 or 4)
    constexpr int WNT = BN / 2;            // warp tile N (64 or 32)
    constexpr int NT  = WNT / 8;           // 8 or 4
    constexpr int MT  = 4;                 // warp tile M = 64

    extern __shared__ float smf[];
    const uint32_t sbase = smem_u32(smf);

    const int tid  = threadIdx.x;
    const int lane = tid & 31;
    const int wid  = tid >> 5;
    const int wm   = wid & 1;              // 2 warps along M
    const int wn   = wid >> 1;             // 2 warps along N
    const int bm   = blockIdx.y * 128;
    const int bn   = blockIdx.x * BN;

    const int mA = tid >> 3;               // 0..15 (+16 per iter)
    const int cA = tid & 7;                // 16B chunk within 128B row
    const int nk = K / 32;

    auto issue = [&](int kt, int s) {
        const uint32_t so = (uint32_t)s * (STW * 4u);
        const int k0 = kt * 32;
#pragma unroll
        for (int i = 0; i < ACH; i++) {
            const int m = mA + 16 * i;
            const uint32_t dst = sbase + so + (uint32_t)m * 128u + (uint32_t)((cA ^ (m & 7)) << 4);
            cp16(dst, A + (size_t)(bm + m) * K + k0 + cA * 4);
        }
#pragma unroll
        for (int i = 0; i < BCH; i++) {
            const int m = mA + 16 * i;
            const uint32_t dst = sbase + so + AW * 4u
                               + (uint32_t)m * 128u + (uint32_t)((cA ^ (m & 7)) << 4);
            cp16(dst, B + (size_t)(bn + m) * K + k0 + cA * 4);
        }
    };

    float acc[MT][NT][4];
#pragma unroll
    for (int i = 0; i < MT; i++)
#pragma unroll
        for (int j = 0; j < NT; j++)
#pragma unroll
            for (int t = 0; t < 4; t++) acc[i][j][t] = 0.f;

    issue(0, 0); CP_COMMIT();
    issue(1, 1); CP_COMMIT();

    // fragment byte-offset bases (stage-local); m&7 == (lane>>2)&7 for all rows
    const uint32_t kkl4 = (uint32_t)(lane & 3) << 2;
    const uint32_t sw4  = (uint32_t)((lane >> 2) & 7) << 4;
    uint32_t abase[MT], bbase[NT];
#pragma unroll
    for (int i = 0; i < MT; i++) {
        const int m0 = wm * 64 + i * 16 + (lane >> 2);
        abase[i] = (uint32_t)m0 * 128u + sw4 + kkl4;
    }
#pragma unroll
    for (int j = 0; j < NT; j++) {
        const int n0 = wn * WNT + j * 8 + (lane >> 2);
        bbase[j] = (uint32_t)n0 * 128u + sw4 + kkl4;
    }

    for (int kt = 0; kt < nk; kt++) {
        const int s = kt % 3;
        if (kt + 2 < nk) issue(kt + 2, (kt + 2) % 3);
        CP_COMMIT();
        CP_WAIT2();
        __syncthreads();

        const uint32_t sa = sbase + (uint32_t)s * (STW * 4u);
        const uint32_t sb = sa + AW * 4u;

#pragma unroll
        for (int ks = 0; ks < 4; ks++) {
            const uint32_t c0 = (uint32_t)(2 * ks) << 4;       // compile-time
            const uint32_t c1 = (uint32_t)(2 * ks + 1) << 4;   // compile-time
            unsigned af[MT][4], bf[NT][2];
#pragma unroll
            for (int i = 0; i < MT; i++) {
                const uint32_t a0 = sa + (abase[i] ^ c0);
                const uint32_t a1 = sa + (abase[i] ^ c1);
                af[i][0] = f2tf(__uint_as_float(lds_u32(a0)));
                af[i][1] = f2tf(__uint_as_float(lds_u32(a0 + 1024u)));
                af[i][2] = f2tf(__uint_as_float(lds_u32(a1)));
                af[i][3] = f2tf(__uint_as_float(lds_u32(a1 + 1024u)));
            }
#pragma unroll
            for (int j = 0; j < NT; j++) {
                bf[j][0] = f2tf(__uint_as_float(lds_u32(sb + (bbase[j] ^ c0))));
                bf[j][1] = f2tf(__uint_as_float(lds_u32(sb + (bbase[j] ^ c1))));
            }
#pragma unroll
            for (int i = 0; i < MT; i++)
#pragma unroll
                for (int j = 0; j < NT; j++)
                    mma_tf32(acc[i][j], af[i], bf[j]);
        }
        __syncthreads();
    }

    // epilogue
#pragma unroll
    for (int i = 0; i < MT; i++) {
#pragma unroll
        for (int j = 0; j < NT; j++) {
            const int r0 = bm + wm * 64 + i * 16 + (lane >> 2);
            const int c0 = bn + wn * WNT + j * 8 + (lane & 3) * 2;
            float2 v0 = make_float2(acc[i][j][0], acc[i][j][1]);
            float2 v1 = make_float2(acc[i][j][2], acc[i][j][3]);
            if (RES) {
                float2 ra = *(const float2*)&Res[(size_t)r0 * N + c0];
                float2 rb = *(const float2*)&Res[(size_t)(r0 + 8) * N + c0];
                v0.x += ra.x; v0.y += ra.y;
                v1.x += rb.x; v1.y += rb.y;
            }
            *(float2*)&C[(size_t)r0 * N + c0] = v0;
            *(float2*)&C[(size_t)(r0 + 8) * N + c0] = v1;
        }
    }
}

// ---------------- attention pass A: scores + global min ----------------
constexpr int QPAD = DMODEL + 4;

extern __shared__ float dynsmem[];

__global__ void __launch_bounds__(256) attn_scores_kernel() {
    float* qs = dynsmem;
    float* ks = dynsmem + MODAL * QPAD;
    const int b = blockIdx.x, tid = threadIdx.x;
    const float4* qg = (const float4*)(g_q + (size_t)b * MODAL * DMODEL);
    const float4* kg = (const float4*)(g_k + (size_t)b * MODAL * DMODEL);
    for (int i = tid; i < MODAL * DMODEL / 4; i += 256) {
        int m = i >> 8, c = i & 255;
        *(float4*)&qs[m * QPAD + c * 4] = qg[i];
        *(float4*)&ks[m * QPAD + c * 4] = kg[i];
    }
    __syncthreads();

    float lmin = 3.4e38f;
    for (int s = tid; s < NHEAD * MODAL * MODAL; s += 256) {
        int h = s >> 6, m = (s >> 3) & 7, n = s & 7;
        const float4* qr = (const float4*)&qs[m * QPAD + h * DK];
        const float4* kr = (const float4*)&ks[n * QPAD + h * DK];
        float acc = 0.f;
#pragma unroll
        for (int d = 0; d < 16; d++) {
            float4 a = qr[d], c = kr[d];
            acc += a.x * c.x + a.y * c.y + a.z * c.z + a.w * c.w;
        }
        acc *= 0.125f;
        g_scores[(size_t)b * 1024 + s] = acc;
        lmin = fminf(lmin, acc);
    }
#pragma unroll
    for (int o = 16; o; o >>= 1) lmin = fminf(lmin, __shfl_xor_sync(0xffffffffu, lmin, o));
    __shared__ float wmn[8];
    if ((tid & 31) == 0) wmn[tid >> 5] = lmin;
    __syncthreads();
    if (tid == 0) {
        float m = wmn[0];
#pragma unroll
        for (int i = 1; i < 8; i++) m = fminf(m, wmn[i]);
        atomicMin(&g_min_u, enc_min(m));
    }
}

// ---------------- attention pass B ----------------
__global__ void __launch_bounds__(256) attn_out_kernel() {
    __shared__ float vs[MODAL * QPAD];
    __shared__ float sc[NHEAD * 64];
    __shared__ float aw[NHEAD * 64];
    const int b = blockIdx.x, tid = threadIdx.x;
    const float inv = 1.f / fabsf(dec_min(g_min_u));

    const float4* vg = (const float4*)(g_v + (size_t)b * MODAL * DMODEL);
    for (int i = tid; i < MODAL * DMODEL / 4; i += 256) {
        int m = i >> 8, c = i & 255;
        *(float4*)&vs[m * QPAD + c * 4] = vg[i];
    }
    for (int i = tid; i < 1024; i += 256)
        sc[i] = g_scores[(size_t)b * 1024 + i] * inv;
    __syncthreads();

    if (tid < 128) {
        int h = tid >> 3, m = tid & 7;
        float r[8]; float ss = 0.f;
#pragma unroll
        for (int n = 0; n < 8; n++) { r[n] = sc[h * 64 + m * 8 + n]; ss += r[n] * r[n]; }
        float nrm = fmaxf(sqrtf(ss), 1e-12f);
        float rn = 1.f / nrm;
        float mx = -3.4e38f;
#pragma unroll
        for (int n = 0; n < 8; n++) { r[n] *= rn; mx = fmaxf(mx, r[n]); }
        float sum = 0.f;
#pragma unroll
        for (int n = 0; n < 8; n++) { r[n] = expf(r[n] - mx); sum += r[n]; }
        float is = 1.f / sum;
#pragma unroll
        for (int n = 0; n < 8; n++) aw[h * 64 + m * 8 + n] = r[n] * is;
    }
    __syncthreads();

    float* og = g_att + (size_t)b * MODAL * DMODEL;
    for (int o = tid; o < MODAL * DMODEL; o += 256) {
        int m = o >> 10, col = o & 1023, h = col >> 6;
        float acc = 0.f;
#pragma unroll
        for (int n = 0; n < 8; n++) acc += aw[h * 64 + m * 8 + n] * vs[n * QPAD + col];
        og[o] = acc;
    }
}

// ---------------- LayerNorm (biased var, eps=1e-10) ----------------
__global__ void __launch_bounds__(256) ln_kernel(
    const float* __restrict__ gamma, const float* __restrict__ beta,
    float* __restrict__ out)
{
    const int wid = threadIdx.x >> 5, lane = threadIdx.x & 31;
    const size_t row = (size_t)blockIdx.x * 8 + wid;
    const float4* xr = (const float4*)(g_x + row * DMODEL);
    float4 v[8];
    float s = 0.f, s2 = 0.f;
#pragma unroll
    for (int i = 0; i < 8; i++) {
        v[i] = xr[lane + 32 * i];
        s += v[i].x + v[i].y + v[i].z + v[i].w;
        s2 += v[i].x * v[i].x + v[i].y * v[i].y + v[i].z * v[i].z + v[i].w * v[i].w;
    }
#pragma unroll
    for (int o = 16; o; o >>= 1) {
        s += __shfl_xor_sync(0xffffffffu, s, o);
        s2 += __shfl_xor_sync(0xffffffffu, s2, o);
    }
    const float mu = s * (1.f / DMODEL);
    const float var = fmaxf(s2 * (1.f / DMODEL) - mu * mu, 0.f);
    const float rs = rsqrtf(var + 1e-10f);
    float4* orow = (float4*)(out + row * DMODEL);
    const float4* gm = (const float4*)gamma;
    const float4* bt = (const float4*)beta;
#pragma unroll
    for (int i = 0; i < 8; i++) {
        int c4 = lane + 32 * i;
        float4 g = gm[c4], bb = bt[c4], x = v[i], r;
        r.x = (x.x - mu) * rs * g.x + bb.x;
        r.y = (x.y - mu) * rs * g.y + bb.y;
        r.z = (x.z - mu) * rs * g.z + bb.z;
        r.w = (x.w - mu) * rs * g.w + bb.w;
        orow[c4] = r;
    }
}

// ---------------- ExternalAttention normalization ----------------
__global__ void __launch_bounds__(64) ext_norm_kernel() {
    const int b = blockIdx.x, s = threadIdx.x;
    __shared__ float sm[MODAL][SEXT];
    __shared__ float rsum[MODAL];
    float xv[MODAL];
    float mx = -3.4e38f;
#pragma unroll
    for (int m = 0; m < MODAL; m++) {
        xv[m] = g_xa[((size_t)b * MODAL + m) * SEXT + s];
        mx = fmaxf(mx, xv[m]);
    }
    float sum = 0.f;
#pragma unroll
    for (int m = 0; m < MODAL; m++) { xv[m] = expf(xv[m] - mx); sum += xv[m]; }
    const float is = 1.f / sum;
#pragma unroll
    for (int m = 0; m < MODAL; m++) sm[m][s] = xv[m] * is;
    __syncthreads();
    if (s < MODAL) {
        float t = 0.f;
        for (int j = 0; j < SEXT; j++) t += sm[s][j];
        rsum[s] = 1.f / t;
    }
    __syncthreads();
#pragma unroll
    for (int m = 0; m < MODAL; m++)
        g_a[((size_t)b * MODAL + m) * SEXT + s] = sm[m][s] * rsum[m];
}

// ---------------- launch ----------------
extern "C" void kernel_launch(void* const* d_in, const int* in_sizes, int n_in,
                              void* d_out, int out_size)
{
    const float* q     = (const float*)d_in[0];
    const float* k     = (const float*)d_in[1];
    const float* v     = (const float*)d_in[2];
    const float* Wq    = (const float*)d_in[3];
    const float* Wk    = (const float*)d_in[4];
    const float* Wv    = (const float*)d_in[5];
    const float* Wfc   = (const float*)d_in[6];
    const float* gamma = (const float*)d_in[7];
    const float* beta  = (const float*)d_in[8];
    const float* Wmk   = (const float*)d_in[9];
    const float* Wmv   = (const float*)d_in[10];
    float* out = (float*)d_out;

    float *pq, *pk, *pv, *patt, *px, *pxa, *pa;
    cudaGetSymbolAddress((void**)&pq,   g_q);
    cudaGetSymbolAddress((void**)&pk,   g_k);
    cudaGetSymbolAddress((void**)&pv,   g_v);
    cudaGetSymbolAddress((void**)&patt, g_att);
    cudaGetSymbolAddress((void**)&px,   g_x);
    cudaGetSymbolAddress((void**)&pxa,  g_xa);
    cudaGetSymbolAddress((void**)&pa,   g_a);

    const int smem_sc = 2 * MODAL * QPAD * (int)sizeof(float);
    cudaFuncSetAttribute(attn_scores_kernel,
                         cudaFuncAttributeMaxDynamicSharedMemorySize, smem_sc);

    const int smem128 = 3 * (128 * 32 + 128 * 32) * (int)sizeof(float);  // 98304
    const int smem64  = 3 * (128 * 32 + 64 * 32) * (int)sizeof(float);   // 73728
    cudaFuncSetAttribute(gemm_ca<128, false>,
                         cudaFuncAttributeMaxDynamicSharedMemorySize, smem128);
    cudaFuncSetAttribute(gemm_ca<128, true>,
                         cudaFuncAttributeMaxDynamicSharedMemorySize, smem128);
    cudaFuncSetAttribute(gemm_ca<64, false>,
                         cudaFuncAttributeMaxDynamicSharedMemorySize, smem64);

    init_min_kernel<<<1, 1>>>();

    dim3 g1(DMODEL / 128, ROWS / 128);  // (8, 256)
    gemm_ca<128, false><<<g1, 128, smem128>>>(q, Wq, nullptr, pq, DMODEL, DMODEL);
    gemm_ca<128, false><<<g1, 128, smem128>>>(k, Wk, nullptr, pk, DMODEL, DMODEL);
    gemm_ca<128, false><<<g1, 128, smem128>>>(v, Wv, nullptr, pv, DMODEL, DMODEL);

    attn_scores_kernel<<<BSZ, 256, smem_sc>>>();
    attn_out_kernel<<<BSZ, 256>>>();

    // x = attn_out @ Wfc^T + q (residual)
    gemm_ca<128, true><<<g1, 128, smem128>>>(patt, Wfc, q, px, DMODEL, DMODEL);

    // LayerNorm -> d_out (this is 'x' for external attention)
    ln_kernel<<<ROWS / 8, 256>>>(gamma, beta, out);

    // xa = x @ Wmk^T  (N=64)
    gemm_ca<64, false><<<dim3(1, ROWS / 128), 128, smem64>>>(out, Wmk, nullptr, pxa,
                                                             DMODEL, SEXT);
    ext_norm_kernel<<<BSZ, 64>>>();

    // out = x + a @ Wmv^T  (K=64)
    gemm_ca<128, true><<<dim3(DMODEL / 128, ROWS / 128), 128, smem128>>>(pa, Wmv, out, out,
                                                                         SEXT, DMODEL);
}

// round 6
// speedup vs baseline: 1.6282x; 1.5634x over previous
#include <cuda_runtime.h>
#include <cuda_fp16.h>
#include <cstdint>

// ---------------- problem constants ----------------
constexpr int MODAL  = 8;
constexpr int DMODEL = 1024;
constexpr int NHEAD  = 16;
constexpr int DK     = 64;
constexpr int SEXT   = 64;
constexpr int BSZ    = 4096;
constexpr int ROWS   = BSZ * MODAL;   // 32768

// ---------------- scratch (device globals) ----------------
__device__ float g_q  [(size_t)ROWS * DMODEL];
__device__ float g_k  [(size_t)ROWS * DMODEL];
__device__ float g_v  [(size_t)ROWS * DMODEL];
__device__ float g_x  [(size_t)ROWS * DMODEL];
__device__ float g_scores[(size_t)BSZ * NHEAD * MODAL * MODAL];
__device__ float g_xa [(size_t)ROWS * SEXT];
// fp16 operands
__device__ __half g_qh [(size_t)ROWS * DMODEL];
__device__ __half g_kh [(size_t)ROWS * DMODEL];
__device__ __half g_vh [(size_t)ROWS * DMODEL];
__device__ __half g_atth[(size_t)ROWS * DMODEL];
__device__ __half g_xh [(size_t)ROWS * DMODEL];
__device__ __half g_ah [(size_t)ROWS * SEXT];
__device__ __half g_wqh [(size_t)DMODEL * DMODEL];
__device__ __half g_wkh [(size_t)DMODEL * DMODEL];
__device__ __half g_wvh [(size_t)DMODEL * DMODEL];
__device__ __half g_wfch[(size_t)DMODEL * DMODEL];
__device__ __half g_wmkh[(size_t)SEXT * DMODEL];
__device__ __half g_wmvh[(size_t)DMODEL * SEXT];
__device__ unsigned g_min_u;

// ---------------- global atomic-min encoding ----------------
__device__ __forceinline__ unsigned enc_min(float f) {
    unsigned u = __float_as_uint(f);
    return (u & 0x80000000u) ? ~u : (u | 0x80000000u);
}
__device__ __forceinline__ float dec_min(unsigned k) {
    return (k & 0x80000000u) ? __uint_as_float(k ^ 0x80000000u)
                             : __uint_as_float(~k);
}
__global__ void init_min_kernel() { g_min_u = 0xFFFFFFFFu; }

// ---------------- helpers ----------------
__device__ __forceinline__ void mma_f16(float* c, const unsigned* a, const unsigned* b) {
    asm volatile(
        "mma.sync.aligned.m16n8k16.row.col.f32.f16.f16.f32 "
        "{%0,%1,%2,%3}, {%4,%5,%6,%7}, {%8,%9}, {%0,%1,%2,%3};\n"
        : "+f"(c[0]), "+f"(c[1]), "+f"(c[2]), "+f"(c[3])
        : "r"(a[0]), "r"(a[1]), "r"(a[2]), "r"(a[3]),
          "r"(b[0]), "r"(b[1]));
}
__device__ __forceinline__ uint32_t smem_u32(const void* p) {
    uint32_t a;
    asm("{ .reg .u64 t; cvta.to.shared.u64 t, %1; cvt.u32.u64 %0, t; }" : "=r"(a) : "l"(p));
    return a;
}
__device__ __forceinline__ unsigned lds_u32(uint32_t a) {
    unsigned v;
    asm volatile("ld.shared.b32 %0, [%1];" : "=r"(v) : "r"(a));
    return v;
}
__device__ __forceinline__ void cp16(uint32_t dst, const void* src) {
    asm volatile("cp.async.cg.shared.global [%0], [%1], 16;" :: "r"(dst), "l"(src));
}
#define CP_COMMIT() asm volatile("cp.async.commit_group;" ::: "memory")
#define CP_WAIT2()  asm volatile("cp.async.wait_group 2;" ::: "memory")

// ---------------- fp32 -> fp16 streaming conversion ----------------
__global__ void __launch_bounds__(256) cvt_h_kernel(
    const float4* __restrict__ s, __half2* __restrict__ d, int n4)
{
    int i = blockIdx.x * 256 + threadIdx.x;
    if (i < n4) {
        float4 v = s[i];
        d[2 * i]     = __float22half2_rn(make_float2(v.x, v.y));
        d[2 * i + 1] = __float22half2_rn(make_float2(v.z, v.w));
    }
}

// =====================================================================
// NT GEMM, fp16 operands, fp32 accumulate:
// C[M,N] = A[M,K] * B[N,K]^T (+ Res fp32). BM=128, BK=64, BN in {128,64}.
// 256 thr = 8 warps (4 M x 2 N), warp tile 32 x (BN/2).
// smem row = 64 halves = 128B; word(m,16Bchunk) swizzle: chunk ^ (m&7).
// cp.async 16B stores and all fragment LDS are bank-conflict-free.
// =====================================================================
template<int BN, bool RES>
__global__ void __launch_bounds__(256, 2) gemm_h(
    const __half* __restrict__ A, const __half* __restrict__ B,
    const float* __restrict__ Res, float* __restrict__ C, int K, int N)
{
    constexpr int ABYTES = 128 * 128;        // A stage bytes (128 rows x 128B)
    constexpr int BBYTES = BN * 128;
    constexpr int STB    = ABYTES + BBYTES;  // stage bytes
    constexpr int BCH    = BN * 8 / 256;     // B chunks per thread (4 or 2)
    constexpr int WNT    = BN / 2;
    constexpr int NT     = WNT / 8;          // 8 or 4
    constexpr int MT     = 2;                // warp tile M = 32

    extern __shared__ char smc[];
    const uint32_t sbase = smem_u32(smc);

    const int tid  = threadIdx.x;
    const int lane = tid & 31;
    const int wid  = tid >> 5;
    const int wm   = wid & 3;
    const int wn   = wid >> 2;
    const int bm   = blockIdx.y * 128;
    const int bn   = blockIdx.x * BN;

    const int mA = tid >> 3;                 // 0..31
    const int cA = tid & 7;                  // 16B chunk (8 halves)
    const int nk = K / 64;

    auto issue = [&](int kt, int s) {
        const uint32_t so = (uint32_t)s * STB;
        const int k0 = kt * 64;
#pragma unroll
        for (int i = 0; i < 4; i++) {
            const int m = mA + 32 * i;
            const uint32_t dst = sbase + so + (uint32_t)m * 128u + (uint32_t)((cA ^ (m & 7)) << 4);
            cp16(dst, A + (size_t)(bm + m) * K + k0 + cA * 8);
        }
#pragma unroll
        for (int i = 0; i < BCH; i++) {
            const int m = mA + 32 * i;
            const uint32_t dst = sbase + so + (uint32_t)ABYTES
                               + (uint32_t)m * 128u + (uint32_t)((cA ^ (m & 7)) << 4);
            cp16(dst, B + (size_t)(bn + m) * K + k0 + cA * 8);
        }
    };

    float acc[MT][NT][4];
#pragma unroll
    for (int i = 0; i < MT; i++)
#pragma unroll
        for (int j = 0; j < NT; j++)
#pragma unroll
            for (int t = 0; t < 4; t++) acc[i][j][t] = 0.f;

    issue(0, 0); CP_COMMIT();
    if (nk > 1) issue(1, 1);
    CP_COMMIT();

    // fragment byte-offset bases (stage-local)
    const uint32_t kkl4 = (uint32_t)(lane & 3) << 2;   // word within 16B chunk
    const uint32_t sw4  = (uint32_t)((lane >> 2) & 7) << 4;
    uint32_t abase[MT], bbase[NT];
#pragma unroll
    for (int i = 0; i < MT; i++) {
        const int m0 = wm * 32 + i * 16 + (lane >> 2);
        abase[i] = (uint32_t)m0 * 128u + sw4 + kkl4;
    }
#pragma unroll
    for (int j = 0; j < NT; j++) {
        const int n0 = wn * WNT + j * 8 + (lane >> 2);
        bbase[j] = (uint32_t)n0 * 128u + sw4 + kkl4;
    }

    for (int kt = 0; kt < nk; kt++) {
        const int s = kt % 3;
        if (kt + 2 < nk) issue(kt + 2, (kt + 2) % 3);
        CP_COMMIT();
        CP_WAIT2();
        __syncthreads();

        const uint32_t sa = sbase + (uint32_t)s * STB;
        const uint32_t sb = sa + ABYTES;

#pragma unroll
        for (int ks = 0; ks < 4; ks++) {               // k = 16 per step
            const uint32_t c0 = (uint32_t)(2 * ks) << 4;
            const uint32_t c1 = (uint32_t)(2 * ks + 1) << 4;
            unsigned af[MT][4], bf[NT][2];
#pragma unroll
            for (int i = 0; i < MT; i++) {
                const uint32_t a0 = sa + (abase[i] ^ c0);
                const uint32_t a1 = sa + (abase[i] ^ c1);
                af[i][0] = lds_u32(a0);            // (r,   k0..k0+1)
                af[i][1] = lds_u32(a0 + 1024u);    // (r+8, k0..k0+1)
                af[i][2] = lds_u32(a1);            // (r,   k0+8..9)
                af[i][3] = lds_u32(a1 + 1024u);    // (r+8, k0+8..9)
            }
#pragma unroll
            for (int j = 0; j < NT; j++) {
                bf[j][0] = lds_u32(sb + (bbase[j] ^ c0));
                bf[j][1] = lds_u32(sb + (bbase[j] ^ c1));
            }
#pragma unroll
            for (int i = 0; i < MT; i++)
#pragma unroll
                for (int j = 0; j < NT; j++)
                    mma_f16(acc[i][j], af[i], bf[j]);
        }
        __syncthreads();
    }

    // epilogue
#pragma unroll
    for (int i = 0; i < MT; i++) {
#pragma unroll
        for (int j = 0; j < NT; j++) {
            const int r0 = bm + wm * 32 + i * 16 + (lane >> 2);
            const int c0 = bn + wn * WNT + j * 8 + (lane & 3) * 2;
            float2 v0 = make_float2(acc[i][j][0], acc[i][j][1]);
            float2 v1 = make_float2(acc[i][j][2], acc[i][j][3]);
            if (RES) {
                float2 ra = *(const float2*)&Res[(size_t)r0 * N + c0];
                float2 rb = *(const float2*)&Res[(size_t)(r0 + 8) * N + c0];
                v0.x += ra.x; v0.y += ra.y;
                v1.x += rb.x; v1.y += rb.y;
            }
            *(float2*)&C[(size_t)r0 * N + c0] = v0;
            *(float2*)&C[(size_t)(r0 + 8) * N + c0] = v1;
        }
    }
}

// ---------------- attention pass A: scores + global min ----------------
constexpr int QPAD = DMODEL + 4;

extern __shared__ float dynsmem[];

__global__ void __launch_bounds__(256) attn_scores_kernel() {
    float* qs = dynsmem;
    float* ks = dynsmem + MODAL * QPAD;
    const int b = blockIdx.x, tid = threadIdx.x;
    const float4* qg = (const float4*)(g_q + (size_t)b * MODAL * DMODEL);
    const float4* kg = (const float4*)(g_k + (size_t)b * MODAL * DMODEL);
    for (int i = tid; i < MODAL * DMODEL / 4; i += 256) {
        int m = i >> 8, c = i & 255;
        *(float4*)&qs[m * QPAD + c * 4] = qg[i];
        *(float4*)&ks[m * QPAD + c * 4] = kg[i];
    }
    __syncthreads();

    float lmin = 3.4e38f;
    for (int s = tid; s < NHEAD * MODAL * MODAL; s += 256) {
        int h = s >> 6, m = (s >> 3) & 7, n = s & 7;
        const float4* qr = (const float4*)&qs[m * QPAD + h * DK];
        const float4* kr = (const float4*)&ks[n * QPAD + h * DK];
        float acc = 0.f;
#pragma unroll
        for (int d = 0; d < 16; d++) {
            float4 a = qr[d], c = kr[d];
            acc += a.x * c.x + a.y * c.y + a.z * c.z + a.w * c.w;
        }
        acc *= 0.125f;
        g_scores[(size_t)b * 1024 + s] = acc;
        lmin = fminf(lmin, acc);
    }
#pragma unroll
    for (int o = 16; o; o >>= 1) lmin = fminf(lmin, __shfl_xor_sync(0xffffffffu, lmin, o));
    __shared__ float wmn[8];
    if ((tid & 31) == 0) wmn[tid >> 5] = lmin;
    __syncthreads();
    if (tid == 0) {
        float m = wmn[0];
#pragma unroll
        for (int i = 1; i < 8; i++) m = fminf(m, wmn[i]);
        atomicMin(&g_min_u, enc_min(m));
    }
}

// ---------------- attention pass B (fp16 output for FC GEMM) ----------------
__global__ void __launch_bounds__(256) attn_out_kernel() {
    __shared__ float vs[MODAL * QPAD];
    __shared__ float sc[NHEAD * 64];
    __shared__ float aw[NHEAD * 64];
    const int b = blockIdx.x, tid = threadIdx.x;
    const float inv = 1.f / fabsf(dec_min(g_min_u));

    const float4* vg = (const float4*)(g_v + (size_t)b * MODAL * DMODEL);
    for (int i = tid; i < MODAL * DMODEL / 4; i += 256) {
        int m = i >> 8, c = i & 255;
        *(float4*)&vs[m * QPAD + c * 4] = vg[i];
    }
    for (int i = tid; i < 1024; i += 256)
        sc[i] = g_scores[(size_t)b * 1024 + i] * inv;
    __syncthreads();

    if (tid < 128) {
        int h = tid >> 3, m = tid & 7;
        float r[8]; float ss = 0.f;
#pragma unroll
        for (int n = 0; n < 8; n++) { r[n] = sc[h * 64 + m * 8 + n]; ss += r[n] * r[n]; }
        float nrm = fmaxf(sqrtf(ss), 1e-12f);
        float rn = 1.f / nrm;
        float mx = -3.4e38f;
#pragma unroll
        for (int n = 0; n < 8; n++) { r[n] *= rn; mx = fmaxf(mx, r[n]); }
        float sum = 0.f;
#pragma unroll
        for (int n = 0; n < 8; n++) { r[n] = expf(r[n] - mx); sum += r[n]; }
        float is = 1.f / sum;
#pragma unroll
        for (int n = 0; n < 8; n++) aw[h * 64 + m * 8 + n] = r[n] * is;
    }
    __syncthreads();

    __half* og = g_atth + (size_t)b * MODAL * DMODEL;
    for (int o = tid; o < MODAL * DMODEL; o += 256) {
        int m = o >> 10, col = o & 1023, h = col >> 6;
        float acc = 0.f;
#pragma unroll
        for (int n = 0; n < 8; n++) acc += aw[h * 64 + m * 8 + n] * vs[n * QPAD + col];
        og[o] = __float2half_rn(acc);
    }
}

// ---------------- LayerNorm: exact fp32 -> out, fp16 copy -> g_xh ----------------
__global__ void __launch_bounds__(256) ln_kernel(
    const float* __restrict__ gamma, const float* __restrict__ beta,
    float* __restrict__ out)
{
    const int wid = threadIdx.x >> 5, lane = threadIdx.x & 31;
    const size_t row = (size_t)blockIdx.x * 8 + wid;
    const float4* xr = (const float4*)(g_x + row * DMODEL);
    float4 v[8];
    float s = 0.f, s2 = 0.f;
#pragma unroll
    for (int i = 0; i < 8; i++) {
        v[i] = xr[lane + 32 * i];
        s += v[i].x + v[i].y + v[i].z + v[i].w;
        s2 += v[i].x * v[i].x + v[i].y * v[i].y + v[i].z * v[i].z + v[i].w * v[i].w;
    }
#pragma unroll
    for (int o = 16; o; o >>= 1) {
        s += __shfl_xor_sync(0xffffffffu, s, o);
        s2 += __shfl_xor_sync(0xffffffffu, s2, o);
    }
    const float mu = s * (1.f / DMODEL);
    const float var = fmaxf(s2 * (1.f / DMODEL) - mu * mu, 0.f);
    const float rs = rsqrtf(var + 1e-10f);
    float4* orow = (float4*)(out + row * DMODEL);
    __half2* hrow = (__half2*)(g_xh + row * DMODEL);
    const float4* gm = (const float4*)gamma;
    const float4* bt = (const float4*)beta;
#pragma unroll
    for (int i = 0; i < 8; i++) {
        int c4 = lane + 32 * i;
        float4 g = gm[c4], bb = bt[c4], x = v[i], r;
        r.x = (x.x - mu) * rs * g.x + bb.x;
        r.y = (x.y - mu) * rs * g.y + bb.y;
        r.z = (x.z - mu) * rs * g.z + bb.z;
        r.w = (x.w - mu) * rs * g.w + bb.w;
        orow[c4] = r;
        hrow[2 * c4]     = __float22half2_rn(make_float2(r.x, r.y));
        hrow[2 * c4 + 1] = __float22half2_rn(make_float2(r.z, r.w));
    }
}

// ---------------- ExternalAttention normalization (fp16 output) ----------------
__global__ void __launch_bounds__(64) ext_norm_kernel() {
    const int b = blockIdx.x, s = threadIdx.x;
    __shared__ float sm[MODAL][SEXT];
    __shared__ float rsum[MODAL];
    float xv[MODAL];
    float mx = -3.4e38f;
#pragma unroll
    for (int m = 0; m < MODAL; m++) {
        xv[m] = g_xa[((size_t)b * MODAL + m) * SEXT + s];
        mx = fmaxf(mx, xv[m]);
    }
    float sum = 0.f;
#pragma unroll
    for (int m = 0; m < MODAL; m++) { xv[m] = expf(xv[m] - mx); sum += xv[m]; }
    const float is = 1.f / sum;
#pragma unroll
    for (int m = 0; m < MODAL; m++) sm[m][s] = xv[m] * is;
    __syncthreads();
    if (s < MODAL) {
        float t = 0.f;
        for (int j = 0; j < SEXT; j++) t += sm[s][j];
        rsum[s] = 1.f / t;
    }
    __syncthreads();
#pragma unroll
    for (int m = 0; m < MODAL; m++)
        g_ah[((size_t)b * MODAL + m) * SEXT + s] = __float2half_rn(sm[m][s] * rsum[m]);
}

// ---------------- launch ----------------
extern "C" void kernel_launch(void* const* d_in, const int* in_sizes, int n_in,
                              void* d_out, int out_size)
{
    const float* q     = (const float*)d_in[0];
    const float* k     = (const float*)d_in[1];
    const float* v     = (const float*)d_in[2];
    const float* Wq    = (const float*)d_in[3];
    const float* Wk    = (const float*)d_in[4];
    const float* Wv    = (const float*)d_in[5];
    const float* Wfc   = (const float*)d_in[6];
    const float* gamma = (const float*)d_in[7];
    const float* beta  = (const float*)d_in[8];
    const float* Wmk   = (const float*)d_in[9];
    const float* Wmv   = (const float*)d_in[10];
    float* out = (float*)d_out;

    float *pq, *pk, *pv, *px, *pxa;
    __half *pqh, *pkh, *pvh, *patth, *pxh, *pah;
    __half *pwqh, *pwkh, *pwvh, *pwfch, *pwmkh, *pwmvh;
    cudaGetSymbolAddress((void**)&pq,    g_q);
    cudaGetSymbolAddress((void**)&pk,    g_k);
    cudaGetSymbolAddress((void**)&pv,    g_v);
    cudaGetSymbolAddress((void**)&px,    g_x);
    cudaGetSymbolAddress((void**)&pxa,   g_xa);
    cudaGetSymbolAddress((void**)&pqh,   g_qh);
    cudaGetSymbolAddress((void**)&pkh,   g_kh);
    cudaGetSymbolAddress((void**)&pvh,   g_vh);
    cudaGetSymbolAddress((void**)&patth, g_atth);
    cudaGetSymbolAddress((void**)&pxh,   g_xh);
    cudaGetSymbolAddress((void**)&pah,   g_ah);
    cudaGetSymbolAddress((void**)&pwqh,  g_wqh);
    cudaGetSymbolAddress((void**)&pwkh,  g_wkh);
    cudaGetSymbolAddress((void**)&pwvh,  g_wvh);
    cudaGetSymbolAddress((void**)&pwfch, g_wfch);
    cudaGetSymbolAddress((void**)&pwmkh, g_wmkh);
    cudaGetSymbolAddress((void**)&pwmvh, g_wmvh);

    const int smem_sc = 2 * MODAL * QPAD * (int)sizeof(float);
    cudaFuncSetAttribute(attn_scores_kernel,
                         cudaFuncAttributeMaxDynamicSharedMemorySize, smem_sc);

    const int smem128 = 3 * (128 * 128 + 128 * 128);  // 98304 B
    const int smem64  = 3 * (128 * 128 + 64 * 128);   // 73728 B
    cudaFuncSetAttribute(gemm_h<128, false>,
                         cudaFuncAttributeMaxDynamicSharedMemorySize, smem128);
    cudaFuncSetAttribute(gemm_h<128, true>,
                         cudaFuncAttributeMaxDynamicSharedMemorySize, smem128);
    cudaFuncSetAttribute(gemm_h<64, false>,
                         cudaFuncAttributeMaxDynamicSharedMemorySize, smem64);

    init_min_kernel<<<1, 1>>>();

    // fp32 -> fp16 conversions (activations + weights)
    const int a4 = ROWS * DMODEL / 4;     // 8M float4
    const int w4 = DMODEL * DMODEL / 4;
    const int s4 = SEXT * DMODEL / 4;
    cvt_h_kernel<<<(a4 + 255) / 256, 256>>>((const float4*)q,   (__half2*)pqh,   a4);
    cvt_h_kernel<<<(a4 + 255) / 256, 256>>>((const float4*)k,   (__half2*)pkh,   a4);
    cvt_h_kernel<<<(a4 + 255) / 256, 256>>>((const float4*)v,   (__half2*)pvh,   a4);
    cvt_h_kernel<<<(w4 + 255) / 256, 256>>>((const float4*)Wq,  (__half2*)pwqh,  w4);
    cvt_h_kernel<<<(w4 + 255) / 256, 256>>>((const float4*)Wk,  (__half2*)pwkh,  w4);
    cvt_h_kernel<<<(w4 + 255) / 256, 256>>>((const float4*)Wv,  (__half2*)pwvh,  w4);
    cvt_h_kernel<<<(w4 + 255) / 256, 256>>>((const float4*)Wfc, (__half2*)pwfch, w4);
    cvt_h_kernel<<<(s4 + 255) / 256, 256>>>((const float4*)Wmk, (__half2*)pwmkh, s4);
    cvt_h_kernel<<<(s4 + 255) / 256, 256>>>((const float4*)Wmv, (__half2*)pwmvh, s4);

    dim3 g1(DMODEL / 128, ROWS / 128);  // (8, 256)
    gemm_h<128, false><<<g1, 256, smem128>>>(pqh, pwqh, nullptr, pq, DMODEL, DMODEL);
    gemm_h<128, false><<<g1, 256, smem128>>>(pkh, pwkh, nullptr, pk, DMODEL, DMODEL);
    gemm_h<128, false><<<g1, 256, smem128>>>(pvh, pwvh, nullptr, pv, DMODEL, DMODEL);

    attn_scores_kernel<<<BSZ, 256, smem_sc>>>();
    attn_out_kernel<<<BSZ, 256>>>();

    // x = attn_out @ Wfc^T + q (residual fp32)
    gemm_h<128, true><<<g1, 256, smem128>>>(patth, pwfch, q, px, DMODEL, DMODEL);

    // LayerNorm -> out (fp32) + g_xh (fp16)
    ln_kernel<<<ROWS / 8, 256>>>(gamma, beta, out);

    // xa = x @ Wmk^T (N=64)
    gemm_h<64, false><<<dim3(1, ROWS / 128), 256, smem64>>>(pxh, pwmkh, nullptr, pxa,
                                                            DMODEL, SEXT);
    ext_norm_kernel<<<BSZ, 64>>>();

    // out = x + a @ Wmv^T (K=64)
    gemm_h<128, true><<<dim3(DMODEL / 128, ROWS / 128), 256, smem128>>>(pah, pwmvh, out, out,
                                                                        SEXT, DMODEL);
}

// round 7
// speedup vs baseline: 1.9797x; 1.2159x over previous
#include <cuda_runtime.h>
#include <cuda_fp16.h>
#include <cstdint>

// ---------------- problem constants ----------------
constexpr int MODAL  = 8;
constexpr int DMODEL = 1024;
constexpr int NHEAD  = 16;
constexpr int DK     = 64;
constexpr int SEXT   = 64;
constexpr int BSZ    = 4096;
constexpr int ROWS   = BSZ * MODAL;   // 32768

// ---------------- scratch (device globals) ----------------
__device__ float g_q  [(size_t)ROWS * DMODEL];
__device__ float g_k  [(size_t)ROWS * DMODEL];
__device__ float g_v  [(size_t)ROWS * DMODEL];
__device__ float g_x  [(size_t)ROWS * DMODEL];
__device__ float g_scores[(size_t)BSZ * NHEAD * MODAL * MODAL];
__device__ float g_xa [(size_t)ROWS * SEXT];
// fp16 operands
__device__ __half g_qh [(size_t)ROWS * DMODEL];
__device__ __half g_kh [(size_t)ROWS * DMODEL];
__device__ __half g_vh [(size_t)ROWS * DMODEL];
__device__ __half g_atth[(size_t)ROWS * DMODEL];
__device__ __half g_xh [(size_t)ROWS * DMODEL];
__device__ __half g_ah [(size_t)ROWS * SEXT];
__device__ __half g_wqh [(size_t)DMODEL * DMODEL];
__device__ __half g_wkh [(size_t)DMODEL * DMODEL];
__device__ __half g_wvh [(size_t)DMODEL * DMODEL];
__device__ __half g_wfch[(size_t)DMODEL * DMODEL];
__device__ __half g_wmkh[(size_t)SEXT * DMODEL];
__device__ __half g_wmvh[(size_t)DMODEL * SEXT];
__device__ unsigned g_min_u;

// ---------------- global atomic-min encoding ----------------
__device__ __forceinline__ unsigned enc_min(float f) {
    unsigned u = __float_as_uint(f);
    return (u & 0x80000000u) ? ~u : (u | 0x80000000u);
}
__device__ __forceinline__ float dec_min(unsigned k) {
    return (k & 0x80000000u) ? __uint_as_float(k ^ 0x80000000u)
                             : __uint_as_float(~k);
}
__global__ void init_min_kernel() { g_min_u = 0xFFFFFFFFu; }

// ---------------- helpers ----------------
__device__ __forceinline__ void mma_f16(float* c, const unsigned* a, const unsigned* b) {
    asm volatile(
        "mma.sync.aligned.m16n8k16.row.col.f32.f16.f16.f32 "
        "{%0,%1,%2,%3}, {%4,%5,%6,%7}, {%8,%9}, {%0,%1,%2,%3};\n"
        : "+f"(c[0]), "+f"(c[1]), "+f"(c[2]), "+f"(c[3])
        : "r"(a[0]), "r"(a[1]), "r"(a[2]), "r"(a[3]),
          "r"(b[0]), "r"(b[1]));
}
__device__ __forceinline__ void ldsm4(unsigned& r0, unsigned& r1, unsigned& r2, unsigned& r3,
                                      uint32_t a) {
    asm volatile("ldmatrix.sync.aligned.m8n8.x4.shared.b16 {%0,%1,%2,%3}, [%4];"
                 : "=r"(r0), "=r"(r1), "=r"(r2), "=r"(r3) : "r"(a));
}
__device__ __forceinline__ uint32_t smem_u32(const void* p) {
    uint32_t a;
    asm("{ .reg .u64 t; cvta.to.shared.u64 t, %1; cvt.u32.u64 %0, t; }" : "=r"(a) : "l"(p));
    return a;
}
__device__ __forceinline__ void cp16(uint32_t dst, const void* src) {
    asm volatile("cp.async.cg.shared.global [%0], [%1], 16;" :: "r"(dst), "l"(src));
}
#define CP_COMMIT() asm volatile("cp.async.commit_group;" ::: "memory")
#define CP_WAIT2()  asm volatile("cp.async.wait_group 2;" ::: "memory")

// ---------------- fp32 -> fp16 streaming conversion ----------------
__global__ void __launch_bounds__(256) cvt_h_kernel(
    const float4* __restrict__ s, __half2* __restrict__ d, int n4)
{
    int i = blockIdx.x * 256 + threadIdx.x;
    if (i < n4) {
        float4 v = s[i];
        d[2 * i]     = __float22half2_rn(make_float2(v.x, v.y));
        d[2 * i + 1] = __float22half2_rn(make_float2(v.z, v.w));
    }
}

// =====================================================================
// NT GEMM, fp16 operands, fp32 accumulate, ldmatrix fragment loads.
// C[M,N] = A[M,K] * B[N,K]^T (+ Res fp32). BM=128, BK=64, BN in {128,64}.
// 256 thr = 8 warps (4 M x 2 N), warp tile 32 x (BN/2).
// smem row = 64 halves = 128B; swizzle off(row,chunk)=row*128+(((row&7)^chunk)<<4);
// per-ks address = laneBase ^ ((2ks)<<4) (chunk-parity folded into laneBase).
// =====================================================================
template<int BN, bool RES>
__global__ void __launch_bounds__(256, 2) gemm_h(
    const __half* __restrict__ A, const __half* __restrict__ B,
    const float* __restrict__ Res, float* __restrict__ C, int K, int N)
{
    constexpr int ABYTES = 128 * 128;        // A stage bytes
    constexpr int BBYTES = BN * 128;
    constexpr int STB    = ABYTES + BBYTES;
    constexpr int BCH    = BN * 8 / 256;     // B cp.async chunks per thread
    constexpr int WNT    = BN / 2;
    constexpr int NT     = WNT / 8;          // 8 or 4
    constexpr int MT     = 2;                // warp tile M = 32

    extern __shared__ char smc[];
    const uint32_t sbase = smem_u32(smc);

    const int tid  = threadIdx.x;
    const int lane = tid & 31;
    const int wid  = tid >> 5;
    const int wm   = wid & 3;
    const int wn   = wid >> 2;
    const int bm   = blockIdx.y * 128;
    const int bn   = blockIdx.x * BN;

    const int mA = tid >> 3;                 // 0..31
    const int cA = tid & 7;                  // 16B chunk
    const int nk = K / 64;

    auto issue = [&](int kt, int s) {
        const uint32_t so = (uint32_t)s * STB;
        const int k0 = kt * 64;
#pragma unroll
        for (int i = 0; i < 4; i++) {
            const int m = mA + 32 * i;
            const uint32_t dst = sbase + so + (uint32_t)m * 128u + (uint32_t)((cA ^ (m & 7)) << 4);
            cp16(dst, A + (size_t)(bm + m) * K + k0 + cA * 8);
        }
#pragma unroll
        for (int i = 0; i < BCH; i++) {
            const int m = mA + 32 * i;
            const uint32_t dst = sbase + so + (uint32_t)ABYTES
                               + (uint32_t)m * 128u + (uint32_t)((cA ^ (m & 7)) << 4);
            cp16(dst, B + (size_t)(bn + m) * K + k0 + cA * 8);
        }
    };

    float acc[MT][NT][4];
#pragma unroll
    for (int i = 0; i < MT; i++)
#pragma unroll
        for (int j = 0; j < NT; j++)
#pragma unroll
            for (int t = 0; t < 4; t++) acc[i][j][t] = 0.f;

    issue(0, 0); CP_COMMIT();
    if (nk > 1) issue(1, 1);
    CP_COMMIT();

    // ---- ldmatrix per-lane base offsets (stage-local bytes) ----
    // A tile i: lane groups g=lane>>3: rows m0+(g&1)*8+(lane&7), chunk parity g>>1
    uint32_t aaddr[MT];
    {
        const int g = lane >> 3;
        const int arow_in = (g & 1) * 8 + (lane & 7);
        const uint32_t apar = (uint32_t)(g >> 1);           // chunk parity bit
#pragma unroll
        for (int i = 0; i < MT; i++) {
            const int row = wm * 32 + i * 16 + arow_in;
            aaddr[i] = (uint32_t)row * 128u + ((((uint32_t)row & 7u) ^ apar) << 4);
        }
    }
    // B pair jp (tiles 2jp, 2jp+1): n = n0 + (g>>1)*8 + (lane&7), chunk parity g&1
    uint32_t baddr[NT / 2];
    {
        const int g = lane >> 3;
        const int nrow_in = ((g >> 1) & 1) * 8 + (lane & 7);
        const uint32_t bpar = (uint32_t)(g & 1);
#pragma unroll
        for (int jp = 0; jp < NT / 2; jp++) {
            const int n = wn * WNT + jp * 16 + nrow_in;
            baddr[jp] = (uint32_t)n * 128u + ((((uint32_t)n & 7u) ^ bpar) << 4);
        }
    }

    for (int kt = 0; kt < nk; kt++) {
        const int s = kt % 3;
        if (kt + 2 < nk) issue(kt + 2, (kt + 2) % 3);
        CP_COMMIT();
        CP_WAIT2();
        __syncthreads();

        const uint32_t sa = sbase + (uint32_t)s * STB;
        const uint32_t sb = sa + ABYTES;

#pragma unroll
        for (int ks = 0; ks < 4; ks++) {               // k = 16 per step
            const uint32_t kx = (uint32_t)(2 * ks) << 4;   // compile-time
            unsigned af[MT][4], bf[NT][2];
#pragma unroll
            for (int i = 0; i < MT; i++)
                ldsm4(af[i][0], af[i][1], af[i][2], af[i][3], sa + (aaddr[i] ^ kx));
#pragma unroll
            for (int jp = 0; jp < NT / 2; jp++)
                ldsm4(bf[2 * jp][0], bf[2 * jp][1], bf[2 * jp + 1][0], bf[2 * jp + 1][1],
                      sb + (baddr[jp] ^ kx));
#pragma unroll
            for (int i = 0; i < MT; i++)
#pragma unroll
                for (int j = 0; j < NT; j++)
                    mma_f16(acc[i][j], af[i], bf[j]);
        }
        __syncthreads();
    }

    // epilogue
#pragma unroll
    for (int i = 0; i < MT; i++) {
#pragma unroll
        for (int j = 0; j < NT; j++) {
            const int r0 = bm + wm * 32 + i * 16 + (lane >> 2);
            const int c0 = bn + wn * WNT + j * 8 + (lane & 3) * 2;
            float2 v0 = make_float2(acc[i][j][0], acc[i][j][1]);
            float2 v1 = make_float2(acc[i][j][2], acc[i][j][3]);
            if (RES) {
                float2 ra = *(const float2*)&Res[(size_t)r0 * N + c0];
                float2 rb = *(const float2*)&Res[(size_t)(r0 + 8) * N + c0];
                v0.x += ra.x; v0.y += ra.y;
                v1.x += rb.x; v1.y += rb.y;
            }
            *(float2*)&C[(size_t)r0 * N + c0] = v0;
            *(float2*)&C[(size_t)(r0 + 8) * N + c0] = v1;
        }
    }
}

// ---------------- attention pass A: scores + global min ----------------
constexpr int QPAD = DMODEL + 4;

extern __shared__ float dynsmem[];

__global__ void __launch_bounds__(256) attn_scores_kernel() {
    float* qs = dynsmem;
    float* ks = dynsmem + MODAL * QPAD;
    const int b = blockIdx.x, tid = threadIdx.x;
    const float4* qg = (const float4*)(g_q + (size_t)b * MODAL * DMODEL);
    const float4* kg = (const float4*)(g_k + (size_t)b * MODAL * DMODEL);
    for (int i = tid; i < MODAL * DMODEL / 4; i += 256) {
        int m = i >> 8, c = i & 255;
        *(float4*)&qs[m * QPAD + c * 4] = qg[i];
        *(float4*)&ks[m * QPAD + c * 4] = kg[i];
    }
    __syncthreads();

    float lmin = 3.4e38f;
    for (int s = tid; s < NHEAD * MODAL * MODAL; s += 256) {
        int h = s >> 6, m = (s >> 3) & 7, n = s & 7;
        const float4* qr = (const float4*)&qs[m * QPAD + h * DK];
        const float4* kr = (const float4*)&ks[n * QPAD + h * DK];
        float acc = 0.f;
#pragma unroll
        for (int d = 0; d < 16; d++) {
            float4 a = qr[d], c = kr[d];
            acc += a.x * c.x + a.y * c.y + a.z * c.z + a.w * c.w;
        }
        acc *= 0.125f;
        g_scores[(size_t)b * 1024 + s] = acc;
        lmin = fminf(lmin, acc);
    }
#pragma unroll
    for (int o = 16; o; o >>= 1) lmin = fminf(lmin, __shfl_xor_sync(0xffffffffu, lmin, o));
    __shared__ float wmn[8];
    if ((tid & 31) == 0) wmn[tid >> 5] = lmin;
    __syncthreads();
    if (tid == 0) {
        float m = wmn[0];
#pragma unroll
        for (int i = 1; i < 8; i++) m = fminf(m, wmn[i]);
        atomicMin(&g_min_u, enc_min(m));
    }
}

// ---------------- attention pass B (fp16 output for FC GEMM) ----------------
__global__ void __launch_bounds__(256) attn_out_kernel() {
    __shared__ float vs[MODAL * QPAD];
    __shared__ float sc[NHEAD * 64];
    __shared__ float aw[NHEAD * 64];
    const int b = blockIdx.x, tid = threadIdx.x;
    const float inv = 1.f / fabsf(dec_min(g_min_u));

    const float4* vg = (const float4*)(g_v + (size_t)b * MODAL * DMODEL);
    for (int i = tid; i < MODAL * DMODEL / 4; i += 256) {
        int m = i >> 8, c = i & 255;
        *(float4*)&vs[m * QPAD + c * 4] = vg[i];
    }
    for (int i = tid; i < 1024; i += 256)
        sc[i] = g_scores[(size_t)b * 1024 + i] * inv;
    __syncthreads();

    if (tid < 128) {
        int h = tid >> 3, m = tid & 7;
        float r[8]; float ss = 0.f;
#pragma unroll
        for (int n = 0; n < 8; n++) { r[n] = sc[h * 64 + m * 8 + n]; ss += r[n] * r[n]; }
        float nrm = fmaxf(sqrtf(ss), 1e-12f);
        float rn = 1.f / nrm;
        float mx = -3.4e38f;
#pragma unroll
        for (int n = 0; n < 8; n++) { r[n] *= rn; mx = fmaxf(mx, r[n]); }
        float sum = 0.f;
#pragma unroll
        for (int n = 0; n < 8; n++) { r[n] = expf(r[n] - mx); sum += r[n]; }
        float is = 1.f / sum;
#pragma unroll
        for (int n = 0; n < 8; n++) aw[h * 64 + m * 8 + n] = r[n] * is;
    }
    __syncthreads();

    __half* og = g_atth + (size_t)b * MODAL * DMODEL;
    for (int o = tid; o < MODAL * DMODEL; o += 256) {
        int m = o >> 10, col = o & 1023, h = col >> 6;
        float acc = 0.f;
#pragma unroll
        for (int n = 0; n < 8; n++) acc += aw[h * 64 + m * 8 + n] * vs[n * QPAD + col];
        og[o] = __float2half_rn(acc);
    }
}

// ---------------- LayerNorm: exact fp32 -> out, fp16 copy -> g_xh ----------------
__global__ void __launch_bounds__(256) ln_kernel(
    const float* __restrict__ gamma, const float* __restrict__ beta,
    float* __restrict__ out)
{
    const int wid = threadIdx.x >> 5, lane = threadIdx.x & 31;
    const size_t row = (size_t)blockIdx.x * 8 + wid;
    const float4* xr = (const float4*)(g_x + row * DMODEL);
    float4 v[8];
    float s = 0.f, s2 = 0.f;
#pragma unroll
    for (int i = 0; i < 8; i++) {
        v[i] = xr[lane + 32 * i];
        s += v[i].x + v[i].y + v[i].z + v[i].w;
        s2 += v[i].x * v[i].x + v[i].y * v[i].y + v[i].z * v[i].z + v[i].w * v[i].w;
    }
#pragma unroll
    for (int o = 16; o; o >>= 1) {
        s += __shfl_xor_sync(0xffffffffu, s, o);
        s2 += __shfl_xor_sync(0xffffffffu, s2, o);
    }
    const float mu = s * (1.f / DMODEL);
    const float var = fmaxf(s2 * (1.f / DMODEL) - mu * mu, 0.f);
    const float rs = rsqrtf(var + 1e-10f);
    float4* orow = (float4*)(out + row * DMODEL);
    __half2* hrow = (__half2*)(g_xh + row * DMODEL);
    const float4* gm = (const float4*)gamma;
    const float4* bt = (const float4*)beta;
#pragma unroll
    for (int i = 0; i < 8; i++) {
        int c4 = lane + 32 * i;
        float4 g = gm[c4], bb = bt[c4], x = v[i], r;
        r.x = (x.x - mu) * rs * g.x + bb.x;
        r.y = (x.y - mu) * rs * g.y + bb.y;
        r.z = (x.z - mu) * rs * g.z + bb.z;
        r.w = (x.w - mu) * rs * g.w + bb.w;
        orow[c4] = r;
        hrow[2 * c4]     = __float22half2_rn(make_float2(r.x, r.y));
        hrow[2 * c4 + 1] = __float22half2_rn(make_float2(r.z, r.w));
    }
}

// ---------------- ExternalAttention normalization (fp16 output) ----------------
__global__ void __launch_bounds__(64) ext_norm_kernel() {
    const int b = blockIdx.x, s = threadIdx.x;
    __shared__ float sm[MODAL][SEXT];
    __shared__ float rsum[MODAL];
    float xv[MODAL];
    float mx = -3.4e38f;
#pragma unroll
    for (int m = 0; m < MODAL; m++) {
        xv[m] = g_xa[((size_t)b * MODAL + m) * SEXT + s];
        mx = fmaxf(mx, xv[m]);
    }
    float sum = 0.f;
#pragma unroll
    for (int m = 0; m < MODAL; m++) { xv[m] = expf(xv[m] - mx); sum += xv[m]; }
    const float is = 1.f / sum;
#pragma unroll
    for (int m = 0; m < MODAL; m++) sm[m][s] = xv[m] * is;
    __syncthreads();
    if (s < MODAL) {
        float t = 0.f;
        for (int j = 0; j < SEXT; j++) t += sm[s][j];
        rsum[s] = 1.f / t;
    }
    __syncthreads();
#pragma unroll
    for (int m = 0; m < MODAL; m++)
        g_ah[((size_t)b * MODAL + m) * SEXT + s] = __float2half_rn(sm[m][s] * rsum[m]);
}

// ---------------- launch ----------------
extern "C" void kernel_launch(void* const* d_in, const int* in_sizes, int n_in,
                              void* d_out, int out_size)
{
    const float* q     = (const float*)d_in[0];
    const float* k     = (const float*)d_in[1];
    const float* v     = (const float*)d_in[2];
    const float* Wq    = (const float*)d_in[3];
    const float* Wk    = (const float*)d_in[4];
    const float* Wv    = (const float*)d_in[5];
    const float* Wfc   = (const float*)d_in[6];
    const float* gamma = (const float*)d_in[7];
    const float* beta  = (const float*)d_in[8];
    const float* Wmk   = (const float*)d_in[9];
    const float* Wmv   = (const float*)d_in[10];
    float* out = (float*)d_out;

    float *pq, *pk, *pv, *px, *pxa;
    __half *pqh, *pkh, *pvh, *patth, *pxh, *pah;
    __half *pwqh, *pwkh, *pwvh, *pwfch, *pwmkh, *pwmvh;
    cudaGetSymbolAddress((void**)&pq,    g_q);
    cudaGetSymbolAddress((void**)&pk,    g_k);
    cudaGetSymbolAddress((void**)&pv,    g_v);
    cudaGetSymbolAddress((void**)&px,    g_x);
    cudaGetSymbolAddress((void**)&pxa,   g_xa);
    cudaGetSymbolAddress((void**)&pqh,   g_qh);
    cudaGetSymbolAddress((void**)&pkh,   g_kh);
    cudaGetSymbolAddress((void**)&pvh,   g_vh);
    cudaGetSymbolAddress((void**)&patth, g_atth);
    cudaGetSymbolAddress((void**)&pxh,   g_xh);
    cudaGetSymbolAddress((void**)&pah,   g_ah);
    cudaGetSymbolAddress((void**)&pwqh,  g_wqh);
    cudaGetSymbolAddress((void**)&pwkh,  g_wkh);
    cudaGetSymbolAddress((void**)&pwvh,  g_wvh);
    cudaGetSymbolAddress((void**)&pwfch, g_wfch);
    cudaGetSymbolAddress((void**)&pwmkh, g_wmkh);
    cudaGetSymbolAddress((void**)&pwmvh, g_wmvh);

    const int smem_sc = 2 * MODAL * QPAD * (int)sizeof(float);
    cudaFuncSetAttribute(attn_scores_kernel,
                         cudaFuncAttributeMaxDynamicSharedMemorySize, smem_sc);

    const int smem128 = 3 * (128 * 128 + 128 * 128);  // 98304 B
    const int smem64  = 3 * (128 * 128 + 64 * 128);   // 73728 B
    cudaFuncSetAttribute(gemm_h<128, false>,
                         cudaFuncAttributeMaxDynamicSharedMemorySize, smem128);
    cudaFuncSetAttribute(gemm_h<128, true>,
                         cudaFuncAttributeMaxDynamicSharedMemorySize, smem128);
    cudaFuncSetAttribute(gemm_h<64, false>,
                         cudaFuncAttributeMaxDynamicSharedMemorySize, smem64);

    init_min_kernel<<<1, 1>>>();

    // fp32 -> fp16 conversions (activations + weights)
    const int a4 = ROWS * DMODEL / 4;
    const int w4 = DMODEL * DMODEL / 4;
    const int s4 = SEXT * DMODEL / 4;
    cvt_h_kernel<<<(a4 + 255) / 256, 256>>>((const float4*)q,   (__half2*)pqh,   a4);
    cvt_h_kernel<<<(a4 + 255) / 256, 256>>>((const float4*)k,   (__half2*)pkh,   a4);
    cvt_h_kernel<<<(a4 + 255) / 256, 256>>>((const float4*)v,   (__half2*)pvh,   a4);
    cvt_h_kernel<<<(w4 + 255) / 256, 256>>>((const float4*)Wq,  (__half2*)pwqh,  w4);
    cvt_h_kernel<<<(w4 + 255) / 256, 256>>>((const float4*)Wk,  (__half2*)pwkh,  w4);
    cvt_h_kernel<<<(w4 + 255) / 256, 256>>>((const float4*)Wv,  (__half2*)pwvh,  w4);
    cvt_h_kernel<<<(w4 + 255) / 256, 256>>>((const float4*)Wfc, (__half2*)pwfch, w4);
    cvt_h_kernel<<<(s4 + 255) / 256, 256>>>((const float4*)Wmk, (__half2*)pwmkh, s4);
    cvt_h_kernel<<<(s4 + 255) / 256, 256>>>((const float4*)Wmv, (__half2*)pwmvh, s4);

    dim3 g1(DMODEL / 128, ROWS / 128);  // (8, 256)
    gemm_h<128, false><<<g1, 256, smem128>>>(pqh, pwqh, nullptr, pq, DMODEL, DMODEL);
    gemm_h<128, false><<<g1, 256, smem128>>>(pkh, pwkh, nullptr, pk, DMODEL, DMODEL);
    gemm_h<128, false><<<g1, 256, smem128>>>(pvh, pwvh, nullptr, pv, DMODEL, DMODEL);

    attn_scores_kernel<<<BSZ, 256, smem_sc>>>();
    attn_out_kernel<<<BSZ, 256>>>();

    // x = attn_out @ Wfc^T + q (residual fp32)
    gemm_h<128, true><<<g1, 256, smem128>>>(patth, pwfch, q, px, DMODEL, DMODEL);

    // LayerNorm -> out (fp32) + g_xh (fp16)
    ln_kernel<<<ROWS / 8, 256>>>(gamma, beta, out);

    // xa = x @ Wmk^T (N=64)
    gemm_h<64, false><<<dim3(1, ROWS / 128), 256, smem64>>>(pxh, pwmkh, nullptr, pxa,
                                                            DMODEL, SEXT);
    ext_norm_kernel<<<BSZ, 64>>>();

    // out = x + a @ Wmv^T (K=64)
    gemm_h<128, true><<<dim3(DMODEL / 128, ROWS / 128), 256, smem128>>>(pah, pwmvh, out, out,
                                                                        SEXT, DMODEL);
}

// round 8
// speedup vs baseline: 2.0454x; 1.0332x over previous
#include <cuda_runtime.h>
#include <cuda_fp16.h>
#include <cstdint>

// ---------------- problem constants ----------------
constexpr int MODAL  = 8;
constexpr int DMODEL = 1024;
constexpr int NHEAD  = 16;
constexpr int DK     = 64;
constexpr int SEXT   = 64;
constexpr int BSZ    = 4096;
constexpr int ROWS   = BSZ * MODAL;   // 32768

// ---------------- scratch (device globals) ----------------
__device__ float g_x  [(size_t)ROWS * DMODEL];
__device__ float g_scores[(size_t)BSZ * NHEAD * MODAL * MODAL];
__device__ float g_xa [(size_t)ROWS * SEXT];
// fp16 operands
__device__ __half g_qh  [(size_t)ROWS * DMODEL];   // fp16 of input q
__device__ __half g_kh  [(size_t)ROWS * DMODEL];
__device__ __half g_vh  [(size_t)ROWS * DMODEL];
__device__ __half g_qph [(size_t)ROWS * DMODEL];   // fp16 projection outputs
__device__ __half g_kph [(size_t)ROWS * DMODEL];
__device__ __half g_vph [(size_t)ROWS * DMODEL];
__device__ __half g_atth[(size_t)ROWS * DMODEL];
__device__ __half g_xh  [(size_t)ROWS * DMODEL];
__device__ __half g_ah  [(size_t)ROWS * SEXT];
__device__ __half g_wqh [(size_t)DMODEL * DMODEL];
__device__ __half g_wkh [(size_t)DMODEL * DMODEL];
__device__ __half g_wvh [(size_t)DMODEL * DMODEL];
__device__ __half g_wfch[(size_t)DMODEL * DMODEL];
__device__ __half g_wmkh[(size_t)SEXT * DMODEL];
__device__ __half g_wmvh[(size_t)DMODEL * SEXT];
__device__ unsigned g_min_u;

// ---------------- global atomic-min encoding ----------------
__device__ __forceinline__ unsigned enc_min(float f) {
    unsigned u = __float_as_uint(f);
    return (u & 0x80000000u) ? ~u : (u | 0x80000000u);
}
__device__ __forceinline__ float dec_min(unsigned k) {
    return (k & 0x80000000u) ? __uint_as_float(k ^ 0x80000000u)
                             : __uint_as_float(~k);
}
__global__ void init_min_kernel() { g_min_u = 0xFFFFFFFFu; }

// ---------------- helpers ----------------
__device__ __forceinline__ void mma_f16(float* c, const unsigned* a, const unsigned* b) {
    asm volatile(
        "mma.sync.aligned.m16n8k16.row.col.f32.f16.f16.f32 "
        "{%0,%1,%2,%3}, {%4,%5,%6,%7}, {%8,%9}, {%0,%1,%2,%3};\n"
        : "+f"(c[0]), "+f"(c[1]), "+f"(c[2]), "+f"(c[3])
        : "r"(a[0]), "r"(a[1]), "r"(a[2]), "r"(a[3]),
          "r"(b[0]), "r"(b[1]));
}
__device__ __forceinline__ void ldsm4(unsigned& r0, unsigned& r1, unsigned& r2, unsigned& r3,
                                      uint32_t a) {
    asm volatile("ldmatrix.sync.aligned.m8n8.x4.shared.b16 {%0,%1,%2,%3}, [%4];"
                 : "=r"(r0), "=r"(r1), "=r"(r2), "=r"(r3) : "r"(a));
}
__device__ __forceinline__ uint32_t smem_u32(const void* p) {
    uint32_t a;
    asm("{ .reg .u64 t; cvta.to.shared.u64 t, %1; cvt.u32.u64 %0, t; }" : "=r"(a) : "l"(p));
    return a;
}
__device__ __forceinline__ void cp16(uint32_t dst, const void* src) {
    asm volatile("cp.async.cg.shared.global [%0], [%1], 16;" :: "r"(dst), "l"(src));
}
#define CP_COMMIT() asm volatile("cp.async.commit_group;" ::: "memory")
#define CP_WAIT2()  asm volatile("cp.async.wait_group 2;" ::: "memory")

// unpack 8 halves (one uint4) -> two float4 stored at dst, dst+4
__device__ __forceinline__ void h8_to_f8(uint4 u, float* dst) {
    const __half2* hp = (const __half2*)&u;
    float2 f0 = __half22float2(hp[0]);
    float2 f1 = __half22float2(hp[1]);
    float2 f2 = __half22float2(hp[2]);
    float2 f3 = __half22float2(hp[3]);
    *(float4*)dst       = make_float4(f0.x, f0.y, f1.x, f1.y);
    *(float4*)(dst + 4) = make_float4(f2.x, f2.y, f3.x, f3.y);
}

// ---------------- fp32 -> fp16 streaming conversion ----------------
__global__ void __launch_bounds__(256) cvt_h_kernel(
    const float4* __restrict__ s, __half2* __restrict__ d, int n4)
{
    int i = blockIdx.x * 256 + threadIdx.x;
    if (i < n4) {
        float4 v = s[i];
        d[2 * i]     = __float22half2_rn(make_float2(v.x, v.y));
        d[2 * i + 1] = __float22half2_rn(make_float2(v.z, v.w));
    }
}

// =====================================================================
// NT GEMM, fp16 operands, fp32 accumulate, ldmatrix fragment loads.
// C[M,N] = A[M,K] * B[N,K]^T (+ Res fp32). BM=128, BK=64, BN in {128,64}.
// OUTH: write fp16 C (no residual); else fp32 C (+ optional fp32 Res).
// =====================================================================
template<int BN, bool RES, bool OUTH>
__global__ void __launch_bounds__(256, 2) gemm_h(
    const __half* __restrict__ A, const __half* __restrict__ B,
    const float* __restrict__ Res, void* __restrict__ Cv, int K, int N)
{
    constexpr int ABYTES = 128 * 128;
    constexpr int BBYTES = BN * 128;
    constexpr int STB    = ABYTES + BBYTES;
    constexpr int BCH    = BN * 8 / 256;
    constexpr int WNT    = BN / 2;
    constexpr int NT     = WNT / 8;
    constexpr int MT     = 2;

    extern __shared__ char smc[];
    const uint32_t sbase = smem_u32(smc);

    const int tid  = threadIdx.x;
    const int lane = tid & 31;
    const int wid  = tid >> 5;
    const int wm   = wid & 3;
    const int wn   = wid >> 2;
    const int bm   = blockIdx.y * 128;
    const int bn   = blockIdx.x * BN;

    const int mA = tid >> 3;
    const int cA = tid & 7;
    const int nk = K / 64;

    auto issue = [&](int kt, int s) {
        const uint32_t so = (uint32_t)s * STB;
        const int k0 = kt * 64;
#pragma unroll
        for (int i = 0; i < 4; i++) {
            const int m = mA + 32 * i;
            const uint32_t dst = sbase + so + (uint32_t)m * 128u + (uint32_t)((cA ^ (m & 7)) << 4);
            cp16(dst, A + (size_t)(bm + m) * K + k0 + cA * 8);
        }
#pragma unroll
        for (int i = 0; i < BCH; i++) {
            const int m = mA + 32 * i;
            const uint32_t dst = sbase + so + (uint32_t)ABYTES
                               + (uint32_t)m * 128u + (uint32_t)((cA ^ (m & 7)) << 4);
            cp16(dst, B + (size_t)(bn + m) * K + k0 + cA * 8);
        }
    };

    float acc[MT][NT][4];
#pragma unroll
    for (int i = 0; i < MT; i++)
#pragma unroll
        for (int j = 0; j < NT; j++)
#pragma unroll
            for (int t = 0; t < 4; t++) acc[i][j][t] = 0.f;

    issue(0, 0); CP_COMMIT();
    if (nk > 1) issue(1, 1);
    CP_COMMIT();

    uint32_t aaddr[MT];
    {
        const int g = lane >> 3;
        const int arow_in = (g & 1) * 8 + (lane & 7);
        const uint32_t apar = (uint32_t)(g >> 1);
#pragma unroll
        for (int i = 0; i < MT; i++) {
            const int row = wm * 32 + i * 16 + arow_in;
            aaddr[i] = (uint32_t)row * 128u + ((((uint32_t)row & 7u) ^ apar) << 4);
        }
    }
    uint32_t baddr[NT / 2];
    {
        const int g = lane >> 3;
        const int nrow_in = ((g >> 1) & 1) * 8 + (lane & 7);
        const uint32_t bpar = (uint32_t)(g & 1);
#pragma unroll
        for (int jp = 0; jp < NT / 2; jp++) {
            const int n = wn * WNT + jp * 16 + nrow_in;
            baddr[jp] = (uint32_t)n * 128u + ((((uint32_t)n & 7u) ^ bpar) << 4);
        }
    }

    for (int kt = 0; kt < nk; kt++) {
        const int s = kt % 3;
        if (kt + 2 < nk) issue(kt + 2, (kt + 2) % 3);
        CP_COMMIT();
        CP_WAIT2();
        __syncthreads();

        const uint32_t sa = sbase + (uint32_t)s * STB;
        const uint32_t sb = sa + ABYTES;

#pragma unroll
        for (int ks = 0; ks < 4; ks++) {
            const uint32_t kx = (uint32_t)(2 * ks) << 4;
            unsigned af[MT][4], bf[NT][2];
#pragma unroll
            for (int i = 0; i < MT; i++)
                ldsm4(af[i][0], af[i][1], af[i][2], af[i][3], sa + (aaddr[i] ^ kx));
#pragma unroll
            for (int jp = 0; jp < NT / 2; jp++)
                ldsm4(bf[2 * jp][0], bf[2 * jp][1], bf[2 * jp + 1][0], bf[2 * jp + 1][1],
                      sb + (baddr[jp] ^ kx));
#pragma unroll
            for (int i = 0; i < MT; i++)
#pragma unroll
                for (int j = 0; j < NT; j++)
                    mma_f16(acc[i][j], af[i], bf[j]);
        }
        __syncthreads();
    }

    // epilogue
#pragma unroll
    for (int i = 0; i < MT; i++) {
#pragma unroll
        for (int j = 0; j < NT; j++) {
            const int r0 = bm + wm * 32 + i * 16 + (lane >> 2);
            const int c0 = bn + wn * WNT + j * 8 + (lane & 3) * 2;
            float2 v0 = make_float2(acc[i][j][0], acc[i][j][1]);
            float2 v1 = make_float2(acc[i][j][2], acc[i][j][3]);
            if (OUTH) {
                __half* Co = (__half*)Cv;
                *(__half2*)&Co[(size_t)r0 * N + c0]       = __floats2half2_rn(v0.x, v0.y);
                *(__half2*)&Co[(size_t)(r0 + 8) * N + c0] = __floats2half2_rn(v1.x, v1.y);
            } else {
                float* Cf = (float*)Cv;
                if (RES) {
                    float2 ra = *(const float2*)&Res[(size_t)r0 * N + c0];
                    float2 rb = *(const float2*)&Res[(size_t)(r0 + 8) * N + c0];
                    v0.x += ra.x; v0.y += ra.y;
                    v1.x += rb.x; v1.y += rb.y;
                }
                *(float2*)&Cf[(size_t)r0 * N + c0] = v0;
                *(float2*)&Cf[(size_t)(r0 + 8) * N + c0] = v1;
            }
        }
    }
}

// ---------------- attention pass A: scores + global min (fp16 inputs) ----------------
constexpr int QPAD = DMODEL + 4;

extern __shared__ float dynsmem[];

__global__ void __launch_bounds__(256) attn_scores_kernel() {
    float* qs = dynsmem;
    float* ks = dynsmem + MODAL * QPAD;
    const int b = blockIdx.x, tid = threadIdx.x;
    const uint4* qg = (const uint4*)(g_qph + (size_t)b * MODAL * DMODEL);  // 8 halves/uint4
    const uint4* kg = (const uint4*)(g_kph + (size_t)b * MODAL * DMODEL);
    for (int i = tid; i < MODAL * DMODEL / 8; i += 256) {   // 1024 iters
        int m = i >> 7, c = i & 127;
        h8_to_f8(qg[i], &qs[m * QPAD + c * 8]);
        h8_to_f8(kg[i], &ks[m * QPAD + c * 8]);
    }
    __syncthreads();

    float lmin = 3.4e38f;
    for (int s = tid; s < NHEAD * MODAL * MODAL; s += 256) {
        int h = s >> 6, m = (s >> 3) & 7, n = s & 7;
        const float4* qr = (const float4*)&qs[m * QPAD + h * DK];
        const float4* kr = (const float4*)&ks[n * QPAD + h * DK];
        float acc = 0.f;
#pragma unroll
        for (int d = 0; d < 16; d++) {
            float4 a = qr[d], c = kr[d];
            acc += a.x * c.x + a.y * c.y + a.z * c.z + a.w * c.w;
        }
        acc *= 0.125f;
        g_scores[(size_t)b * 1024 + s] = acc;
        lmin = fminf(lmin, acc);
    }
#pragma unroll
    for (int o = 16; o; o >>= 1) lmin = fminf(lmin, __shfl_xor_sync(0xffffffffu, lmin, o));
    __shared__ float wmn[8];
    if ((tid & 31) == 0) wmn[tid >> 5] = lmin;
    __syncthreads();
    if (tid == 0) {
        float m = wmn[0];
#pragma unroll
        for (int i = 1; i < 8; i++) m = fminf(m, wmn[i]);
        atomicMin(&g_min_u, enc_min(m));
    }
}

// ---------------- attention pass B (fp16 v input, fp16 output) ----------------
__global__ void __launch_bounds__(256) attn_out_kernel() {
    __shared__ float vs[MODAL * QPAD];
    __shared__ float sc[NHEAD * 64];
    __shared__ float aw[NHEAD * 64];
    const int b = blockIdx.x, tid = threadIdx.x;
    const float inv = 1.f / fabsf(dec_min(g_min_u));

    const uint4* vg = (const uint4*)(g_vph + (size_t)b * MODAL * DMODEL);
    for (int i = tid; i < MODAL * DMODEL / 8; i += 256) {
        int m = i >> 7, c = i & 127;
        h8_to_f8(vg[i], &vs[m * QPAD + c * 8]);
    }
    for (int i = tid; i < 1024; i += 256)
        sc[i] = g_scores[(size_t)b * 1024 + i] * inv;
    __syncthreads();

    if (tid < 128) {
        int h = tid >> 3, m = tid & 7;
        float r[8]; float ss = 0.f;
#pragma unroll
        for (int n = 0; n < 8; n++) { r[n] = sc[h * 64 + m * 8 + n]; ss += r[n] * r[n]; }
        float nrm = fmaxf(sqrtf(ss), 1e-12f);
        float rn = 1.f / nrm;
        float mx = -3.4e38f;
#pragma unroll
        for (int n = 0; n < 8; n++) { r[n] *= rn; mx = fmaxf(mx, r[n]); }
        float sum = 0.f;
#pragma unroll
        for (int n = 0; n < 8; n++) { r[n] = expf(r[n] - mx); sum += r[n]; }
        float is = 1.f / sum;
#pragma unroll
        for (int n = 0; n < 8; n++) aw[h * 64 + m * 8 + n] = r[n] * is;
    }
    __syncthreads();

    __half* og = g_atth + (size_t)b * MODAL * DMODEL;
    for (int o = tid; o < MODAL * DMODEL; o += 256) {
        int m = o >> 10, col = o & 1023, h = col >> 6;
        float acc = 0.f;
#pragma unroll
        for (int n = 0; n < 8; n++) acc += aw[h * 64 + m * 8 + n] * vs[n * QPAD + col];
        og[o] = __float2half_rn(acc);
    }
}

// ---------------- LayerNorm: exact fp32 -> out, fp16 copy -> g_xh ----------------
__global__ void __launch_bounds__(256) ln_kernel(
    const float* __restrict__ gamma, const float* __restrict__ beta,
    float* __restrict__ out)
{
    const int wid = threadIdx.x >> 5, lane = threadIdx.x & 31;
    const size_t row = (size_t)blockIdx.x * 8 + wid;
    const float4* xr = (const float4*)(g_x + row * DMODEL);
    float4 v[8];
    float s = 0.f, s2 = 0.f;
#pragma unroll
    for (int i = 0; i < 8; i++) {
        v[i] = xr[lane + 32 * i];
        s += v[i].x + v[i].y + v[i].z + v[i].w;
        s2 += v[i].x * v[i].x + v[i].y * v[i].y + v[i].z * v[i].z + v[i].w * v[i].w;
    }
#pragma unroll
    for (int o = 16; o; o >>= 1) {
        s += __shfl_xor_sync(0xffffffffu, s, o);
        s2 += __shfl_xor_sync(0xffffffffu, s2, o);
    }
    const float mu = s * (1.f / DMODEL);
    const float var = fmaxf(s2 * (1.f / DMODEL) - mu * mu, 0.f);
    const float rs = rsqrtf(var + 1e-10f);
    float4* orow = (float4*)(out + row * DMODEL);
    __half2* hrow = (__half2*)(g_xh + row * DMODEL);
    const float4* gm = (const float4*)gamma;
    const float4* bt = (const float4*)beta;
#pragma unroll
    for (int i = 0; i < 8; i++) {
        int c4 = lane + 32 * i;
        float4 g = gm[c4], bb = bt[c4], x = v[i], r;
        r.x = (x.x - mu) * rs * g.x + bb.x;
        r.y = (x.y - mu) * rs * g.y + bb.y;
        r.z = (x.z - mu) * rs * g.z + bb.z;
        r.w = (x.w - mu) * rs * g.w + bb.w;
        orow[c4] = r;
        hrow[2 * c4]     = __float22half2_rn(make_float2(r.x, r.y));
        hrow[2 * c4 + 1] = __float22half2_rn(make_float2(r.z, r.w));
    }
}

// ---------------- ExternalAttention normalization (fp16 output) ----------------
__global__ void __launch_bounds__(64) ext_norm_kernel() {
    const int b = blockIdx.x, s = threadIdx.x;
    __shared__ float sm[MODAL][SEXT];
    __shared__ float rsum[MODAL];
    float xv[MODAL];
    float mx = -3.4e38f;
#pragma unroll
    for (int m = 0; m < MODAL; m++) {
        xv[m] = g_xa[((size_t)b * MODAL + m) * SEXT + s];
        mx = fmaxf(mx, xv[m]);
    }
    float sum = 0.f;
#pragma unroll
    for (int m = 0; m < MODAL; m++) { xv[m] = expf(xv[m] - mx); sum += xv[m]; }
    const float is = 1.f / sum;
#pragma unroll
    for (int m = 0; m < MODAL; m++) sm[m][s] = xv[m] * is;
    __syncthreads();
    if (s < MODAL) {
        float t = 0.f;
        for (int j = 0; j < SEXT; j++) t += sm[s][j];
        rsum[s] = 1.f / t;
    }
    __syncthreads();
#pragma unroll
    for (int m = 0; m < MODAL; m++)
        g_ah[((size_t)b * MODAL + m) * SEXT + s] = __float2half_rn(sm[m][s] * rsum[m]);
}

// ---------------- launch ----------------
extern "C" void kernel_launch(void* const* d_in, const int* in_sizes, int n_in,
                              void* d_out, int out_size)
{
    const float* q     = (const float*)d_in[0];
    const float* k     = (const float*)d_in[1];
    const float* v     = (const float*)d_in[2];
    const float* Wq    = (const float*)d_in[3];
    const float* Wk    = (const float*)d_in[4];
    const float* Wv    = (const float*)d_in[5];
    const float* Wfc   = (const float*)d_in[6];
    const float* gamma = (const float*)d_in[7];
    const float* beta  = (const float*)d_in[8];
    const float* Wmk   = (const float*)d_in[9];
    const float* Wmv   = (const float*)d_in[10];
    float* out = (float*)d_out;

    float *px, *pxa;
    __half *pqh, *pkh, *pvh, *pqph, *pkph, *pvph, *patth, *pxh, *pah;
    __half *pwqh, *pwkh, *pwvh, *pwfch, *pwmkh, *pwmvh;
    cudaGetSymbolAddress((void**)&px,    g_x);
    cudaGetSymbolAddress((void**)&pxa,   g_xa);
    cudaGetSymbolAddress((void**)&pqh,   g_qh);
    cudaGetSymbolAddress((void**)&pkh,   g_kh);
    cudaGetSymbolAddress((void**)&pvh,   g_vh);
    cudaGetSymbolAddress((void**)&pqph,  g_qph);
    cudaGetSymbolAddress((void**)&pkph,  g_kph);
    cudaGetSymbolAddress((void**)&pvph,  g_vph);
    cudaGetSymbolAddress((void**)&patth, g_atth);
    cudaGetSymbolAddress((void**)&pxh,   g_xh);
    cudaGetSymbolAddress((void**)&pah,   g_ah);
    cudaGetSymbolAddress((void**)&pwqh,  g_wqh);
    cudaGetSymbolAddress((void**)&pwkh,  g_wkh);
    cudaGetSymbolAddress((void**)&pwvh,  g_wvh);
    cudaGetSymbolAddress((void**)&pwfch, g_wfch);
    cudaGetSymbolAddress((void**)&pwmkh, g_wmkh);
    cudaGetSymbolAddress((void**)&pwmvh, g_wmvh);

    const int smem_sc = 2 * MODAL * QPAD * (int)sizeof(float);
    cudaFuncSetAttribute(attn_scores_kernel,
                         cudaFuncAttributeMaxDynamicSharedMemorySize, smem_sc);

    const int smem128 = 3 * (128 * 128 + 128 * 128);  // 98304 B
    const int smem64  = 3 * (128 * 128 + 64 * 128);   // 73728 B
    cudaFuncSetAttribute(gemm_h<128, false, true>,
                         cudaFuncAttributeMaxDynamicSharedMemorySize, smem128);
    cudaFuncSetAttribute(gemm_h<128, true, false>,
                         cudaFuncAttributeMaxDynamicSharedMemorySize, smem128);
    cudaFuncSetAttribute(gemm_h<64, false, false>,
                         cudaFuncAttributeMaxDynamicSharedMemorySize, smem64);

    init_min_kernel<<<1, 1>>>();

    // fp32 -> fp16 conversions (activations + weights)
    const int a4 = ROWS * DMODEL / 4;
    const int w4 = DMODEL * DMODEL / 4;
    const int s4 = SEXT * DMODEL / 4;
    cvt_h_kernel<<<(a4 + 255) / 256, 256>>>((const float4*)q,   (__half2*)pqh,   a4);
    cvt_h_kernel<<<(a4 + 255) / 256, 256>>>((const float4*)k,   (__half2*)pkh,   a4);
    cvt_h_kernel<<<(a4 + 255) / 256, 256>>>((const float4*)v,   (__half2*)pvh,   a4);
    cvt_h_kernel<<<(w4 + 255) / 256, 256>>>((const float4*)Wq,  (__half2*)pwqh,  w4);
    cvt_h_kernel<<<(w4 + 255) / 256, 256>>>((const float4*)Wk,  (__half2*)pwkh,  w4);
    cvt_h_kernel<<<(w4 + 255) / 256, 256>>>((const float4*)Wv,  (__half2*)pwvh,  w4);
    cvt_h_kernel<<<(w4 + 255) / 256, 256>>>((const float4*)Wfc, (__half2*)pwfch, w4);
    cvt_h_kernel<<<(s4 + 255) / 256, 256>>>((const float4*)Wmk, (__half2*)pwmkh, s4);
    cvt_h_kernel<<<(s4 + 255) / 256, 256>>>((const float4*)Wmv, (__half2*)pwmvh, s4);

    dim3 g1(DMODEL / 128, ROWS / 128);  // (8, 256)
    // projections -> fp16 outputs
    gemm_h<128, false, true><<<g1, 256, smem128>>>(pqh, pwqh, nullptr, pqph, DMODEL, DMODEL);
    gemm_h<128, false, true><<<g1, 256, smem128>>>(pkh, pwkh, nullptr, pkph, DMODEL, DMODEL);
    gemm_h<128, false, true><<<g1, 256, smem128>>>(pvh, pwvh, nullptr, pvph, DMODEL, DMODEL);

    attn_scores_kernel<<<BSZ, 256, smem_sc>>>();
    attn_out_kernel<<<BSZ, 256>>>();

    // x = attn_out @ Wfc^T + q (residual fp32)
    gemm_h<128, true, false><<<g1, 256, smem128>>>(patth, pwfch, q, px, DMODEL, DMODEL);

    // LayerNorm -> out (fp32) + g_xh (fp16)
    ln_kernel<<<ROWS / 8, 256>>>(gamma, beta, out);

    // xa = x @ Wmk^T (N=64)
    gemm_h<64, false, false><<<dim3(1, ROWS / 128), 256, smem64>>>(pxh, pwmkh, nullptr, pxa,
                                                                   DMODEL, SEXT);
    ext_norm_kernel<<<BSZ, 64>>>();

    // out = x + a @ Wmv^T (K=64)
    gemm_h<128, true, false><<<dim3(DMODEL / 128, ROWS / 128), 256, smem128>>>(pah, pwmvh, out, out,
                                                                               SEXT, DMODEL);
}

// round 9
// speedup vs baseline: 2.0565x; 1.0054x over previous
#include <cuda_runtime.h>
#include <cuda_fp16.h>
#include <cstdint>

// ---------------- problem constants ----------------
constexpr int MODAL  = 8;
constexpr int DMODEL = 1024;
constexpr int NHEAD  = 16;
constexpr int DK     = 64;
constexpr int SEXT   = 64;
constexpr int BSZ    = 4096;
constexpr int ROWS   = BSZ * MODAL;   // 32768

// ---------------- scratch (device globals) ----------------
__device__ float g_scores[(size_t)BSZ * NHEAD * MODAL * MODAL];
__device__ float g_xa [(size_t)ROWS * SEXT];
// fp16 operands
__device__ __half g_qh   [(size_t)ROWS * DMODEL];   // fp16 of input q (also FC residual)
__device__ __half g_kh   [(size_t)ROWS * DMODEL];
__device__ __half g_vh   [(size_t)ROWS * DMODEL];
__device__ __half g_qph  [(size_t)ROWS * DMODEL];   // fp16 projection outputs
__device__ __half g_kph  [(size_t)ROWS * DMODEL];
__device__ __half g_vph  [(size_t)ROWS * DMODEL];
__device__ __half g_atth [(size_t)ROWS * DMODEL];
__device__ __half g_xpreh[(size_t)ROWS * DMODEL];   // pre-LN x (fp16)
__device__ __half g_xh   [(size_t)ROWS * DMODEL];   // post-LN x (fp16, for xa GEMM)
__device__ __half g_ah   [(size_t)ROWS * SEXT];
__device__ __half g_wqh  [(size_t)DMODEL * DMODEL];
__device__ __half g_wkh  [(size_t)DMODEL * DMODEL];
__device__ __half g_wvh  [(size_t)DMODEL * DMODEL];
__device__ __half g_wfch [(size_t)DMODEL * DMODEL];
__device__ __half g_wmkh [(size_t)SEXT * DMODEL];
__device__ __half g_wmvh [(size_t)DMODEL * SEXT];
__device__ unsigned g_min_u;

// ---------------- global atomic-min encoding ----------------
__device__ __forceinline__ unsigned enc_min(float f) {
    unsigned u = __float_as_uint(f);
    return (u & 0x80000000u) ? ~u : (u | 0x80000000u);
}
__device__ __forceinline__ float dec_min(unsigned k) {
    return (k & 0x80000000u) ? __uint_as_float(k ^ 0x80000000u)
                             : __uint_as_float(~k);
}
__global__ void init_min_kernel() { g_min_u = 0xFFFFFFFFu; }

// ---------------- helpers ----------------
__device__ __forceinline__ void mma_f16(float* c, const unsigned* a, const unsigned* b) {
    asm volatile(
        "mma.sync.aligned.m16n8k16.row.col.f32.f16.f16.f32 "
        "{%0,%1,%2,%3}, {%4,%5,%6,%7}, {%8,%9}, {%0,%1,%2,%3};\n"
        : "+f"(c[0]), "+f"(c[1]), "+f"(c[2]), "+f"(c[3])
        : "r"(a[0]), "r"(a[1]), "r"(a[2]), "r"(a[3]),
          "r"(b[0]), "r"(b[1]));
}
__device__ __forceinline__ void ldsm4(unsigned& r0, unsigned& r1, unsigned& r2, unsigned& r3,
                                      uint32_t a) {
    asm volatile("ldmatrix.sync.aligned.m8n8.x4.shared.b16 {%0,%1,%2,%3}, [%4];"
                 : "=r"(r0), "=r"(r1), "=r"(r2), "=r"(r3) : "r"(a));
}
__device__ __forceinline__ uint32_t smem_u32(const void* p) {
    uint32_t a;
    asm("{ .reg .u64 t; cvta.to.shared.u64 t, %1; cvt.u32.u64 %0, t; }" : "=r"(a) : "l"(p));
    return a;
}
__device__ __forceinline__ void cp16(uint32_t dst, const void* src) {
    asm volatile("cp.async.cg.shared.global [%0], [%1], 16;" :: "r"(dst), "l"(src));
}
#define CP_COMMIT() asm volatile("cp.async.commit_group;" ::: "memory")
#define CP_WAIT2()  asm volatile("cp.async.wait_group 2;" ::: "memory")

// unpack 8 halves (one uint4) -> 8 floats
__device__ __forceinline__ void h8_to_f8(uint4 u, float* dst) {
    const __half2* hp = (const __half2*)&u;
    float2 f0 = __half22float2(hp[0]);
    float2 f1 = __half22float2(hp[1]);
    float2 f2 = __half22float2(hp[2]);
    float2 f3 = __half22float2(hp[3]);
    dst[0] = f0.x; dst[1] = f0.y; dst[2] = f1.x; dst[3] = f1.y;
    dst[4] = f2.x; dst[5] = f2.y; dst[6] = f3.x; dst[7] = f3.y;
}

// ---------------- fp32 -> fp16 streaming conversion ----------------
__global__ void __launch_bounds__(256) cvt_h_kernel(
    const float4* __restrict__ s, __half2* __restrict__ d, int n4)
{
    int i = blockIdx.x * 256 + threadIdx.x;
    if (i < n4) {
        float4 v = s[i];
        d[2 * i]     = __float22half2_rn(make_float2(v.x, v.y));
        d[2 * i + 1] = __float22half2_rn(make_float2(v.z, v.w));
    }
}

// =====================================================================
// NT GEMM, fp16 operands, fp32 accumulate, ldmatrix fragment loads.
// C[M,N] = A[M,K] * B[N,K]^T (+ Res). BM=128, BK=64, BN in {128,64}.
// RESM: 0 none, 1 fp32 residual, 2 fp16 residual. OUTH: fp16 C else fp32 C.
// =====================================================================
template<int BN, int RESM, bool OUTH>
__global__ void __launch_bounds__(256, 2) gemm_h(
    const __half* __restrict__ A, const __half* __restrict__ B,
    const void* __restrict__ Resv, void* __restrict__ Cv, int K, int N)
{
    constexpr int ABYTES = 128 * 128;
    constexpr int BBYTES = BN * 128;
    constexpr int STB    = ABYTES + BBYTES;
    constexpr int BCH    = BN * 8 / 256;
    constexpr int WNT    = BN / 2;
    constexpr int NT     = WNT / 8;
    constexpr int MT     = 2;

    extern __shared__ char smc[];
    const uint32_t sbase = smem_u32(smc);

    const int tid  = threadIdx.x;
    const int lane = tid & 31;
    const int wid  = tid >> 5;
    const int wm   = wid & 3;
    const int wn   = wid >> 2;
    const int bm   = blockIdx.y * 128;
    const int bn   = blockIdx.x * BN;

    const int mA = tid >> 3;
    const int cA = tid & 7;
    const int nk = K / 64;

    auto issue = [&](int kt, int s) {
        const uint32_t so = (uint32_t)s * STB;
        const int k0 = kt * 64;
#pragma unroll
        for (int i = 0; i < 4; i++) {
            const int m = mA + 32 * i;
            const uint32_t dst = sbase + so + (uint32_t)m * 128u + (uint32_t)((cA ^ (m & 7)) << 4);
            cp16(dst, A + (size_t)(bm + m) * K + k0 + cA * 8);
        }
#pragma unroll
        for (int i = 0; i < BCH; i++) {
            const int m = mA + 32 * i;
            const uint32_t dst = sbase + so + (uint32_t)ABYTES
                               + (uint32_t)m * 128u + (uint32_t)((cA ^ (m & 7)) << 4);
            cp16(dst, B + (size_t)(bn + m) * K + k0 + cA * 8);
        }
    };

    float acc[MT][NT][4];
#pragma unroll
    for (int i = 0; i < MT; i++)
#pragma unroll
        for (int j = 0; j < NT; j++)
#pragma unroll
            for (int t = 0; t < 4; t++) acc[i][j][t] = 0.f;

    issue(0, 0); CP_COMMIT();
    if (nk > 1) issue(1, 1);
    CP_COMMIT();

    uint32_t aaddr[MT];
    {
        const int g = lane >> 3;
        const int arow_in = (g & 1) * 8 + (lane & 7);
        const uint32_t apar = (uint32_t)(g >> 1);
#pragma unroll
        for (int i = 0; i < MT; i++) {
            const int row = wm * 32 + i * 16 + arow_in;
            aaddr[i] = (uint32_t)row * 128u + ((((uint32_t)row & 7u) ^ apar) << 4);
        }
    }
    uint32_t baddr[NT / 2];
    {
        const int g = lane >> 3;
        const int nrow_in = ((g >> 1) & 1) * 8 + (lane & 7);
        const uint32_t bpar = (uint32_t)(g & 1);
#pragma unroll
        for (int jp = 0; jp < NT / 2; jp++) {
            const int n = wn * WNT + jp * 16 + nrow_in;
            baddr[jp] = (uint32_t)n * 128u + ((((uint32_t)n & 7u) ^ bpar) << 4);
        }
    }

    for (int kt = 0; kt < nk; kt++) {
        const int s = kt % 3;
        if (kt + 2 < nk) issue(kt + 2, (kt + 2) % 3);
        CP_COMMIT();
        CP_WAIT2();
        __syncthreads();

        const uint32_t sa = sbase + (uint32_t)s * STB;
        const uint32_t sb = sa + ABYTES;

#pragma unroll
        for (int ks = 0; ks < 4; ks++) {
            const uint32_t kx = (uint32_t)(2 * ks) << 4;
            unsigned af[MT][4], bf[NT][2];
#pragma unroll
            for (int i = 0; i < MT; i++)
                ldsm4(af[i][0], af[i][1], af[i][2], af[i][3], sa + (aaddr[i] ^ kx));
#pragma unroll
            for (int jp = 0; jp < NT / 2; jp++)
                ldsm4(bf[2 * jp][0], bf[2 * jp][1], bf[2 * jp + 1][0], bf[2 * jp + 1][1],
                      sb + (baddr[jp] ^ kx));
#pragma unroll
            for (int i = 0; i < MT; i++)
#pragma unroll
                for (int j = 0; j < NT; j++)
                    mma_f16(acc[i][j], af[i], bf[j]);
        }
        __syncthreads();
    }

    // epilogue
#pragma unroll
    for (int i = 0; i < MT; i++) {
#pragma unroll
        for (int j = 0; j < NT; j++) {
            const int r0 = bm + wm * 32 + i * 16 + (lane >> 2);
            const int c0 = bn + wn * WNT + j * 8 + (lane & 3) * 2;
            float2 v0 = make_float2(acc[i][j][0], acc[i][j][1]);
            float2 v1 = make_float2(acc[i][j][2], acc[i][j][3]);
            if (RESM == 1) {
                const float* Res = (const float*)Resv;
                float2 ra = *(const float2*)&Res[(size_t)r0 * N + c0];
                float2 rb = *(const float2*)&Res[(size_t)(r0 + 8) * N + c0];
                v0.x += ra.x; v0.y += ra.y;
                v1.x += rb.x; v1.y += rb.y;
            } else if (RESM == 2) {
                const __half* Rh = (const __half*)Resv;
                float2 ra = __half22float2(*(const __half2*)&Rh[(size_t)r0 * N + c0]);
                float2 rb = __half22float2(*(const __half2*)&Rh[(size_t)(r0 + 8) * N + c0]);
                v0.x += ra.x; v0.y += ra.y;
                v1.x += rb.x; v1.y += rb.y;
            }
            if (OUTH) {
                __half* Co = (__half*)Cv;
                *(__half2*)&Co[(size_t)r0 * N + c0]       = __floats2half2_rn(v0.x, v0.y);
                *(__half2*)&Co[(size_t)(r0 + 8) * N + c0] = __floats2half2_rn(v1.x, v1.y);
            } else {
                float* Cf = (float*)Cv;
                *(float2*)&Cf[(size_t)r0 * N + c0] = v0;
                *(float2*)&Cf[(size_t)(r0 + 8) * N + c0] = v1;
            }
        }
    }
}

// ---------------- attention pass A: scores + global min (fp16 inputs) ----------------
constexpr int QPAD = DMODEL + 4;

extern __shared__ float dynsmem[];

__global__ void __launch_bounds__(256) attn_scores_kernel() {
    float* qs = dynsmem;
    float* ks = dynsmem + MODAL * QPAD;
    const int b = blockIdx.x, tid = threadIdx.x;
    const uint4* qg = (const uint4*)(g_qph + (size_t)b * MODAL * DMODEL);
    const uint4* kg = (const uint4*)(g_kph + (size_t)b * MODAL * DMODEL);
    for (int i = tid; i < MODAL * DMODEL / 8; i += 256) {
        int m = i >> 7, c = i & 127;
        h8_to_f8(qg[i], &qs[m * QPAD + c * 8]);
        h8_to_f8(kg[i], &ks[m * QPAD + c * 8]);
    }
    __syncthreads();

    float lmin = 3.4e38f;
    for (int s = tid; s < NHEAD * MODAL * MODAL; s += 256) {
        int h = s >> 6, m = (s >> 3) & 7, n = s & 7;
        const float4* qr = (const float4*)&qs[m * QPAD + h * DK];
        const float4* kr = (const float4*)&ks[n * QPAD + h * DK];
        float acc = 0.f;
#pragma unroll
        for (int d = 0; d < 16; d++) {
            float4 a = qr[d], c = kr[d];
            acc += a.x * c.x + a.y * c.y + a.z * c.z + a.w * c.w;
        }
        acc *= 0.125f;
        g_scores[(size_t)b * 1024 + s] = acc;
        lmin = fminf(lmin, acc);
    }
#pragma unroll
    for (int o = 16; o; o >>= 1) lmin = fminf(lmin, __shfl_xor_sync(0xffffffffu, lmin, o));
    __shared__ float wmn[8];
    if ((tid & 31) == 0) wmn[tid >> 5] = lmin;
    __syncthreads();
    if (tid == 0) {
        float m = wmn[0];
#pragma unroll
        for (int i = 1; i < 8; i++) m = fminf(m, wmn[i]);
        atomicMin(&g_min_u, enc_min(m));
    }
}

// ---------------- attention pass B (fp16 v input, fp16 output) ----------------
__global__ void __launch_bounds__(256) attn_out_kernel() {
    __shared__ float vs[MODAL * QPAD];
    __shared__ float sc[NHEAD * 64];
    __shared__ float aw[NHEAD * 64];
    const int b = blockIdx.x, tid = threadIdx.x;
    const float inv = 1.f / fabsf(dec_min(g_min_u));

    const uint4* vg = (const uint4*)(g_vph + (size_t)b * MODAL * DMODEL);
    for (int i = tid; i < MODAL * DMODEL / 8; i += 256) {
        int m = i >> 7, c = i & 127;
        h8_to_f8(vg[i], &vs[m * QPAD + c * 8]);
    }
    for (int i = tid; i < 1024; i += 256)
        sc[i] = g_scores[(size_t)b * 1024 + i] * inv;
    __syncthreads();

    if (tid < 128) {
        int h = tid >> 3, m = tid & 7;
        float r[8]; float ss = 0.f;
#pragma unroll
        for (int n = 0; n < 8; n++) { r[n] = sc[h * 64 + m * 8 + n]; ss += r[n] * r[n]; }
        float nrm = fmaxf(sqrtf(ss), 1e-12f);
        float rn = 1.f / nrm;
        float mx = -3.4e38f;
#pragma unroll
        for (int n = 0; n < 8; n++) { r[n] *= rn; mx = fmaxf(mx, r[n]); }
        float sum = 0.f;
#pragma unroll
        for (int n = 0; n < 8; n++) { r[n] = expf(r[n] - mx); sum += r[n]; }
        float is = 1.f / sum;
#pragma unroll
        for (int n = 0; n < 8; n++) aw[h * 64 + m * 8 + n] = r[n] * is;
    }
    __syncthreads();

    __half* og = g_atth + (size_t)b * MODAL * DMODEL;
    for (int o = tid; o < MODAL * DMODEL; o += 256) {
        int m = o >> 10, col = o & 1023, h = col >> 6;
        float acc = 0.f;
#pragma unroll
        for (int n = 0; n < 8; n++) acc += aw[h * 64 + m * 8 + n] * vs[n * QPAD + col];
        og[o] = __float2half_rn(acc);
    }
}

// ---------------- LayerNorm: fp16 x in, fp32 out + fp16 copy ----------------
__global__ void __launch_bounds__(256) ln_kernel(
    const float* __restrict__ gamma, const float* __restrict__ beta,
    float* __restrict__ out)
{
    const int wid = threadIdx.x >> 5, lane = threadIdx.x & 31;
    const size_t row = (size_t)blockIdx.x * 8 + wid;
    const uint4* xr = (const uint4*)(g_xpreh + row * DMODEL);  // 128 uint4 per row
    float xv[4][8];
    float s = 0.f, s2 = 0.f;
#pragma unroll
    for (int i = 0; i < 4; i++) {
        h8_to_f8(xr[lane + 32 * i], xv[i]);
#pragma unroll
        for (int j = 0; j < 8; j++) { s += xv[i][j]; s2 += xv[i][j] * xv[i][j]; }
    }
#pragma unroll
    for (int o = 16; o; o >>= 1) {
        s += __shfl_xor_sync(0xffffffffu, s, o);
        s2 += __shfl_xor_sync(0xffffffffu, s2, o);
    }
    const float mu = s * (1.f / DMODEL);
    const float var = fmaxf(s2 * (1.f / DMODEL) - mu * mu, 0.f);
    const float rs = rsqrtf(var + 1e-10f);
    float4* orow = (float4*)(out + row * DMODEL);
    uint4* hrow = (uint4*)(g_xh + row * DMODEL);
    const float4* gm = (const float4*)gamma;
    const float4* bt = (const float4*)beta;
#pragma unroll
    for (int i = 0; i < 4; i++) {
        const int c8 = lane + 32 * i;          // uint4 index (8 floats)
        float r[8];
#pragma unroll
        for (int half4 = 0; half4 < 2; half4++) {
            float4 g = gm[2 * c8 + half4], bb = bt[2 * c8 + half4];
            r[4 * half4 + 0] = (xv[i][4 * half4 + 0] - mu) * rs * g.x + bb.x;
            r[4 * half4 + 1] = (xv[i][4 * half4 + 1] - mu) * rs * g.y + bb.y;
            r[4 * half4 + 2] = (xv[i][4 * half4 + 2] - mu) * rs * g.z + bb.z;
            r[4 * half4 + 3] = (xv[i][4 * half4 + 3] - mu) * rs * g.w + bb.w;
            orow[2 * c8 + half4] = make_float4(r[4 * half4 + 0], r[4 * half4 + 1],
                                               r[4 * half4 + 2], r[4 * half4 + 3]);
        }
        uint4 hpack;
        __half2* hp = (__half2*)&hpack;
        hp[0] = __floats2half2_rn(r[0], r[1]);
        hp[1] = __floats2half2_rn(r[2], r[3]);
        hp[2] = __floats2half2_rn(r[4], r[5]);
        hp[3] = __floats2half2_rn(r[6], r[7]);
        hrow[c8] = hpack;
    }
}

// ---------------- ExternalAttention normalization (fp16 output) ----------------
__global__ void __launch_bounds__(64) ext_norm_kernel() {
    const int b = blockIdx.x, s = threadIdx.x;
    __shared__ float sm[MODAL][SEXT];
    __shared__ float rsum[MODAL];
    float xv[MODAL];
    float mx = -3.4e38f;
#pragma unroll
    for (int m = 0; m < MODAL; m++) {
        xv[m] = g_xa[((size_t)b * MODAL + m) * SEXT + s];
        mx = fmaxf(mx, xv[m]);
    }
    float sum = 0.f;
#pragma unroll
    for (int m = 0; m < MODAL; m++) { xv[m] = expf(xv[m] - mx); sum += xv[m]; }
    const float is = 1.f / sum;
#pragma unroll
    for (int m = 0; m < MODAL; m++) sm[m][s] = xv[m] * is;
    __syncthreads();
    if (s < MODAL) {
        float t = 0.f;
        for (int j = 0; j < SEXT; j++) t += sm[s][j];
        rsum[s] = 1.f / t;
    }
    __syncthreads();
#pragma unroll
    for (int m = 0; m < MODAL; m++)
        g_ah[((size_t)b * MODAL + m) * SEXT + s] = __float2half_rn(sm[m][s] * rsum[m]);
}

// ---------------- launch ----------------
extern "C" void kernel_launch(void* const* d_in, const int* in_sizes, int n_in,
                              void* d_out, int out_size)
{
    const float* q     = (const float*)d_in[0];
    const float* k     = (const float*)d_in[1];
    const float* v     = (const float*)d_in[2];
    const float* Wq    = (const float*)d_in[3];
    const float* Wk    = (const float*)d_in[4];
    const float* Wv    = (const float*)d_in[5];
    const float* Wfc   = (const float*)d_in[6];
    const float* gamma = (const float*)d_in[7];
    const float* beta  = (const float*)d_in[8];
    const float* Wmk   = (const float*)d_in[9];
    const float* Wmv   = (const float*)d_in[10];
    float* out = (float*)d_out;

    float *pxa;
    __half *pqh, *pkh, *pvh, *pqph, *pkph, *pvph, *patth, *pxpreh, *pxh, *pah;
    __half *pwqh, *pwkh, *pwvh, *pwfch, *pwmkh, *pwmvh;
    cudaGetSymbolAddress((void**)&pxa,    g_xa);
    cudaGetSymbolAddress((void**)&pqh,    g_qh);
    cudaGetSymbolAddress((void**)&pkh,    g_kh);
    cudaGetSymbolAddress((void**)&pvh,    g_vh);
    cudaGetSymbolAddress((void**)&pqph,   g_qph);
    cudaGetSymbolAddress((void**)&pkph,   g_kph);
    cudaGetSymbolAddress((void**)&pvph,   g_vph);
    cudaGetSymbolAddress((void**)&patth,  g_atth);
    cudaGetSymbolAddress((void**)&pxpreh, g_xpreh);
    cudaGetSymbolAddress((void**)&pxh,    g_xh);
    cudaGetSymbolAddress((void**)&pah,    g_ah);
    cudaGetSymbolAddress((void**)&pwqh,   g_wqh);
    cudaGetSymbolAddress((void**)&pwkh,   g_wkh);
    cudaGetSymbolAddress((void**)&pwvh,   g_wvh);
    cudaGetSymbolAddress((void**)&pwfch,  g_wfch);
    cudaGetSymbolAddress((void**)&pwmkh,  g_wmkh);
    cudaGetSymbolAddress((void**)&pwmvh,  g_wmvh);

    const int smem_sc = 2 * MODAL * QPAD * (int)sizeof(float);
    cudaFuncSetAttribute(attn_scores_kernel,
                         cudaFuncAttributeMaxDynamicSharedMemorySize, smem_sc);

    const int smem128 = 3 * (128 * 128 + 128 * 128);  // 98304 B
    const int smem64  = 3 * (128 * 128 + 64 * 128);   // 73728 B
    cudaFuncSetAttribute(gemm_h<128, 0, true>,
                         cudaFuncAttributeMaxDynamicSharedMemorySize, smem128);
    cudaFuncSetAttribute(gemm_h<128, 2, true>,
                         cudaFuncAttributeMaxDynamicSharedMemorySize, smem128);
    cudaFuncSetAttribute(gemm_h<128, 1, false>,
                         cudaFuncAttributeMaxDynamicSharedMemorySize, smem128);
    cudaFuncSetAttribute(gemm_h<64, 0, false>,
                         cudaFuncAttributeMaxDynamicSharedMemorySize, smem64);

    init_min_kernel<<<1, 1>>>();

    // fp32 -> fp16 conversions (activations + weights)
    const int a4 = ROWS * DMODEL / 4;
    const int w4 = DMODEL * DMODEL / 4;
    const int s4 = SEXT * DMODEL / 4;
    cvt_h_kernel<<<(a4 + 255) / 256, 256>>>((const float4*)q,   (__half2*)pqh,   a4);
    cvt_h_kernel<<<(a4 + 255) / 256, 256>>>((const float4*)k,   (__half2*)pkh,   a4);
    cvt_h_kernel<<<(a4 + 255) / 256, 256>>>((const float4*)v,   (__half2*)pvh,   a4);
    cvt_h_kernel<<<(w4 + 255) / 256, 256>>>((const float4*)Wq,  (__half2*)pwqh,  w4);
    cvt_h_kernel<<<(w4 + 255) / 256, 256>>>((const float4*)Wk,  (__half2*)pwkh,  w4);
    cvt_h_kernel<<<(w4 + 255) / 256, 256>>>((const float4*)Wv,  (__half2*)pwvh,  w4);
    cvt_h_kernel<<<(w4 + 255) / 256, 256>>>((const float4*)Wfc, (__half2*)pwfch, w4);
    cvt_h_kernel<<<(s4 + 255) / 256, 256>>>((const float4*)Wmk, (__half2*)pwmkh, s4);
    cvt_h_kernel<<<(s4 + 255) / 256, 256>>>((const float4*)Wmv, (__half2*)pwmvh, s4);

    dim3 g1(DMODEL / 128, ROWS / 128);  // (8, 256)
    // projections -> fp16 outputs
    gemm_h<128, 0, true><<<g1, 256, smem128>>>(pqh, pwqh, nullptr, pqph, DMODEL, DMODEL);
    gemm_h<128, 0, true><<<g1, 256, smem128>>>(pkh, pwkh, nullptr, pkph, DMODEL, DMODEL);
    gemm_h<128, 0, true><<<g1, 256, smem128>>>(pvh, pwvh, nullptr, pvph, DMODEL, DMODEL);

    attn_scores_kernel<<<BSZ, 256, smem_sc>>>();
    attn_out_kernel<<<BSZ, 256>>>();

    // x = attn_out @ Wfc^T + q (fp16 residual) -> fp16 xpre
    gemm_h<128, 2, true><<<g1, 256, smem128>>>(patth, pwfch, pqh, pxpreh, DMODEL, DMODEL);

    // LayerNorm (fp16 in) -> out (fp32) + g_xh (fp16)
    ln_kernel<<<ROWS / 8, 256>>>(gamma, beta, out);

    // xa = x @ Wmk^T (N=64)
    gemm_h<64, 0, false><<<dim3(1, ROWS / 128), 256, smem64>>>(pxh, pwmkh, nullptr, pxa,
                                                               DMODEL, SEXT);
    ext_norm_kernel<<<BSZ, 64>>>();

    // out = x + a @ Wmv^T (K=64, fp32 residual = out)
    gemm_h<128, 1, false><<<dim3(DMODEL / 128, ROWS / 128), 256, smem128>>>(pah, pwmvh, out, out,
                                                                            SEXT, DMODEL);
}

// round 11
// speedup vs baseline: 2.0603x; 1.0019x over previous
#include <cuda_runtime.h>
#include <cuda_fp16.h>
#include <cstdint>

// ---------------- problem constants ----------------
constexpr int MODAL  = 8;
constexpr int DMODEL = 1024;
constexpr int NHEAD  = 16;
constexpr int DK     = 64;
constexpr int SEXT   = 64;
constexpr int BSZ    = 4096;
constexpr int ROWS   = BSZ * MODAL;   // 32768

// ---------------- scratch (device globals) ----------------
__device__ float g_x  [(size_t)ROWS * DMODEL];
__device__ float g_scores[(size_t)BSZ * NHEAD * MODAL * MODAL];
// fp16 operands
__device__ __half g_qh  [(size_t)ROWS * DMODEL];
__device__ __half g_kh  [(size_t)ROWS * DMODEL];
__device__ __half g_vh  [(size_t)ROWS * DMODEL];
__device__ __half g_qph [(size_t)ROWS * DMODEL];
__device__ __half g_kph [(size_t)ROWS * DMODEL];
__device__ __half g_vph [(size_t)ROWS * DMODEL];
__device__ __half g_atth[(size_t)ROWS * DMODEL];
__device__ __half g_xh  [(size_t)ROWS * DMODEL];
__device__ __half g_ah  [(size_t)ROWS * SEXT];
__device__ __half g_wqh [(size_t)DMODEL * DMODEL];
__device__ __half g_wkh [(size_t)DMODEL * DMODEL];
__device__ __half g_wvh [(size_t)DMODEL * DMODEL];
__device__ __half g_wfch[(size_t)DMODEL * DMODEL];
__device__ __half g_wmkh[(size_t)SEXT * DMODEL];
__device__ __half g_wmvh[(size_t)DMODEL * SEXT];
__device__ unsigned g_min_u;

// ---------------- global atomic-min encoding ----------------
__device__ __forceinline__ unsigned enc_min(float f) {
    unsigned u = __float_as_uint(f);
    return (u & 0x80000000u) ? ~u : (u | 0x80000000u);
}
__device__ __forceinline__ float dec_min(unsigned k) {
    return (k & 0x80000000u) ? __uint_as_float(k ^ 0x80000000u)
                             : __uint_as_float(~k);
}
__global__ void init_min_kernel() { g_min_u = 0xFFFFFFFFu; }

// ---------------- helpers ----------------
__device__ __forceinline__ void mma_f16(float* c, const unsigned* a, const unsigned* b) {
    asm volatile(
        "mma.sync.aligned.m16n8k16.row.col.f32.f16.f16.f32 "
        "{%0,%1,%2,%3}, {%4,%5,%6,%7}, {%8,%9}, {%0,%1,%2,%3};\n"
        : "+f"(c[0]), "+f"(c[1]), "+f"(c[2]), "+f"(c[3])
        : "r"(a[0]), "r"(a[1]), "r"(a[2]), "r"(a[3]),
          "r"(b[0]), "r"(b[1]));
}
__device__ __forceinline__ void ldsm4(unsigned& r0, unsigned& r1, unsigned& r2, unsigned& r3,
                                      uint32_t a) {
    asm volatile("ldmatrix.sync.aligned.m8n8.x4.shared.b16 {%0,%1,%2,%3}, [%4];"
                 : "=r"(r0), "=r"(r1), "=r"(r2), "=r"(r3) : "r"(a));
}
__device__ __forceinline__ uint32_t smem_u32(const void* p) {
    uint32_t a;
    asm("{ .reg .u64 t; cvta.to.shared.u64 t, %1; cvt.u32.u64 %0, t; }" : "=r"(a) : "l"(p));
    return a;
}
__device__ __forceinline__ void cp16(uint32_t dst, const void* src) {
    asm volatile("cp.async.cg.shared.global [%0], [%1], 16;" :: "r"(dst), "l"(src));
}
#define CP_COMMIT() asm volatile("cp.async.commit_group;" ::: "memory")
#define CP_WAIT2()  asm volatile("cp.async.wait_group 2;" ::: "memory")

// unpack 8 halves (one uint4) -> 8 floats at dst
__device__ __forceinline__ void h8_to_f8(uint4 u, float* dst) {
    const __half2* hp = (const __half2*)&u;
    float2 f0 = __half22float2(hp[0]);
    float2 f1 = __half22float2(hp[1]);
    float2 f2 = __half22float2(hp[2]);
    float2 f3 = __half22float2(hp[3]);
    *(float4*)dst       = make_float4(f0.x, f0.y, f1.x, f1.y);
    *(float4*)(dst + 4) = make_float4(f2.x, f2.y, f3.x, f3.y);
}

// ---------------- fp32 -> fp16 streaming conversion ----------------
__global__ void __launch_bounds__(256) cvt_h_kernel(
    const float4* __restrict__ s, __half2* __restrict__ d, int n4)
{
    int i = blockIdx.x * 256 + threadIdx.x;
    if (i < n4) {
        float4 v = s[i];
        d[2 * i]     = __float22half2_rn(make_float2(v.x, v.y));
        d[2 * i + 1] = __float22half2_rn(make_float2(v.z, v.w));
    }
}

// =====================================================================
// NT GEMM, fp16 operands, fp32 accumulate, ldmatrix fragment loads.
// C[M,N] = A[M,K] * B[N,K]^T (+ Res fp32). BM=128, BK=64, BN in {128,64}.
// OUTH: write fp16 C (no residual); else fp32 C (+ optional fp32 Res).
// =====================================================================
template<int BN, bool RES, bool OUTH>
__global__ void __launch_bounds__(256, 2) gemm_h(
    const __half* __restrict__ A, const __half* __restrict__ B,
    const float* __restrict__ Res, void* __restrict__ Cv, int K, int N)
{
    constexpr int ABYTES = 128 * 128;
    constexpr int BBYTES = BN * 128;
    constexpr int STB    = ABYTES + BBYTES;
    constexpr int BCH    = BN * 8 / 256;
    constexpr int WNT    = BN / 2;
    constexpr int NT     = WNT / 8;
    constexpr int MT     = 2;

    extern __shared__ char smc[];
    const uint32_t sbase = smem_u32(smc);

    const int tid  = threadIdx.x;
    const int lane = tid & 31;
    const int wid  = tid >> 5;
    const int wm   = wid & 3;
    const int wn   = wid >> 2;
    const int bm   = blockIdx.y * 128;
    const int bn   = blockIdx.x * BN;

    const int mA = tid >> 3;
    const int cA = tid & 7;
    const int nk = K / 64;

    auto issue = [&](int kt, int s) {
        const uint32_t so = (uint32_t)s * STB;
        const int k0 = kt * 64;
#pragma unroll
        for (int i = 0; i < 4; i++) {
            const int m = mA + 32 * i;
            const uint32_t dst = sbase + so + (uint32_t)m * 128u + (uint32_t)((cA ^ (m & 7)) << 4);
            cp16(dst, A + (size_t)(bm + m) * K + k0 + cA * 8);
        }
#pragma unroll
        for (int i = 0; i < BCH; i++) {
            const int m = mA + 32 * i;
            const uint32_t dst = sbase + so + (uint32_t)ABYTES
                               + (uint32_t)m * 128u + (uint32_t)((cA ^ (m & 7)) << 4);
            cp16(dst, B + (size_t)(bn + m) * K + k0 + cA * 8);
        }
    };

    float acc[MT][NT][4];
#pragma unroll
    for (int i = 0; i < MT; i++)
#pragma unroll
        for (int j = 0; j < NT; j++)
#pragma unroll
            for (int t = 0; t < 4; t++) acc[i][j][t] = 0.f;

    issue(0, 0); CP_COMMIT();
    if (nk > 1) issue(1, 1);
    CP_COMMIT();

    uint32_t aaddr[MT];
    {
        const int g = lane >> 3;
        const int arow_in = (g & 1) * 8 + (lane & 7);
        const uint32_t apar = (uint32_t)(g >> 1);
#pragma unroll
        for (int i = 0; i < MT; i++) {
            const int row = wm * 32 + i * 16 + arow_in;
            aaddr[i] = (uint32_t)row * 128u + ((((uint32_t)row & 7u) ^ apar) << 4);
        }
    }
    uint32_t baddr[NT / 2];
    {
        const int g = lane >> 3;
        const int nrow_in = ((g >> 1) & 1) * 8 + (lane & 7);
        const uint32_t bpar = (uint32_t)(g & 1);
#pragma unroll
        for (int jp = 0; jp < NT / 2; jp++) {
            const int n = wn * WNT + jp * 16 + nrow_in;
            baddr[jp] = (uint32_t)n * 128u + ((((uint32_t)n & 7u) ^ bpar) << 4);
        }
    }

    for (int kt = 0; kt < nk; kt++) {
        const int s = kt % 3;
        if (kt + 2 < nk) issue(kt + 2, (kt + 2) % 3);
        CP_COMMIT();
        CP_WAIT2();
        __syncthreads();

        const uint32_t sa = sbase + (uint32_t)s * STB;
        const uint32_t sb = sa + ABYTES;

#pragma unroll
        for (int ks = 0; ks < 4; ks++) {
            const uint32_t kx = (uint32_t)(2 * ks) << 4;
            unsigned af[MT][4], bf[NT][2];
#pragma unroll
            for (int i = 0; i < MT; i++)
                ldsm4(af[i][0], af[i][1], af[i][2], af[i][3], sa + (aaddr[i] ^ kx));
#pragma unroll
            for (int jp = 0; jp < NT / 2; jp++)
                ldsm4(bf[2 * jp][0], bf[2 * jp][1], bf[2 * jp + 1][0], bf[2 * jp + 1][1],
                      sb + (baddr[jp] ^ kx));
#pragma unroll
            for (int i = 0; i < MT; i++)
#pragma unroll
                for (int j = 0; j < NT; j++)
                    mma_f16(acc[i][j], af[i], bf[j]);
        }
        __syncthreads();
    }

    // epilogue
#pragma unroll
    for (int i = 0; i < MT; i++) {
#pragma unroll
        for (int j = 0; j < NT; j++) {
            const int r0 = bm + wm * 32 + i * 16 + (lane >> 2);
            const int c0 = bn + wn * WNT + j * 8 + (lane & 3) * 2;
            float2 v0 = make_float2(acc[i][j][0], acc[i][j][1]);
            float2 v1 = make_float2(acc[i][j][2], acc[i][j][3]);
            if (OUTH) {
                __half* Co = (__half*)Cv;
                *(__half2*)&Co[(size_t)r0 * N + c0]       = __floats2half2_rn(v0.x, v0.y);
                *(__half2*)&Co[(size_t)(r0 + 8) * N + c0] = __floats2half2_rn(v1.x, v1.y);
            } else {
                float* Cf = (float*)Cv;
                if (RES) {
                    float2 ra = *(const float2*)&Res[(size_t)r0 * N + c0];
                    float2 rb = *(const float2*)&Res[(size_t)(r0 + 8) * N + c0];
                    v0.x += ra.x; v0.y += ra.y;
                    v1.x += rb.x; v1.y += rb.y;
                }
                *(float2*)&Cf[(size_t)r0 * N + c0] = v0;
                *(float2*)&Cf[(size_t)(r0 + 8) * N + c0] = v1;
            }
        }
    }
}

// =====================================================================
// Fused xa GEMM + ExternalAttention normalization.
// xa = g_xh @ Wmk^T  (128x64 tile per CTA; grid (1, 256), K=1024)
// then per CTA (16 complete batches): softmax over modal rows (groups of
// 8) and renormalize over S=64 columns; emit fp16 a to g_ah.
// =====================================================================
__global__ void __launch_bounds__(256, 2) gemm_xa_ext(
    const __half* __restrict__ A, const __half* __restrict__ B)
{
    constexpr int BN     = 64;
    constexpr int ABYTES = 128 * 128;
    constexpr int BBYTES = BN * 128;
    constexpr int STB    = ABYTES + BBYTES;
    constexpr int BCH    = 2;
    constexpr int WNT    = 32;
    constexpr int NT     = 4;
    constexpr int MT     = 2;
    constexpr int K      = DMODEL;
    constexpr int TP     = 66;   // padded fp32 tile row stride

    extern __shared__ char smc[];
    const uint32_t sbase = smem_u32(smc);

    const int tid  = threadIdx.x;
    const int lane = tid & 31;
    const int wid  = tid >> 5;
    const int wm   = wid & 3;
    const int wn   = wid >> 2;
    const int bm   = blockIdx.y * 128;

    const int mA = tid >> 3;
    const int cA = tid & 7;
    constexpr int nk = K / 64;   // 16

    auto issue = [&](int kt, int s) {
        const uint32_t so = (uint32_t)s * STB;
        const int k0 = kt * 64;
#pragma unroll
        for (int i = 0; i < 4; i++) {
            const int m = mA + 32 * i;
            const uint32_t dst = sbase + so + (uint32_t)m * 128u + (uint32_t)((cA ^ (m & 7)) << 4);
            cp16(dst, A + (size_t)(bm + m) * K + k0 + cA * 8);
        }
#pragma unroll
        for (int i = 0; i < BCH; i++) {
            const int m = mA + 32 * i;
            const uint32_t dst = sbase + so + (uint32_t)ABYTES
                               + (uint32_t)m * 128u + (uint32_t)((cA ^ (m & 7)) << 4);
            cp16(dst, B + (size_t)m * K + k0 + cA * 8);
        }
    };

    float acc[MT][NT][4];
#pragma unroll
    for (int i = 0; i < MT; i++)
#pragma unroll
        for (int j = 0; j < NT; j++)
#pragma unroll
            for (int t = 0; t < 4; t++) acc[i][j][t] = 0.f;

    issue(0, 0); CP_COMMIT();
    issue(1, 1); CP_COMMIT();

    uint32_t aaddr[MT];
    {
        const int g = lane >> 3;
        const int arow_in = (g & 1) * 8 + (lane & 7);
        const uint32_t apar = (uint32_t)(g >> 1);
#pragma unroll
        for (int i = 0; i < MT; i++) {
            const int row = wm * 32 + i * 16 + arow_in;
            aaddr[i] = (uint32_t)row * 128u + ((((uint32_t)row & 7u) ^ apar) << 4);
        }
    }
    uint32_t baddr[NT / 2];
    {
        const int g = lane >> 3;
        const int nrow_in = ((g >> 1) & 1) * 8 + (lane & 7);
        const uint32_t bpar = (uint32_t)(g & 1);
#pragma unroll
        for (int jp = 0; jp < NT / 2; jp++) {
            const int n = wn * WNT + jp * 16 + nrow_in;
            baddr[jp] = (uint32_t)n * 128u + ((((uint32_t)n & 7u) ^ bpar) << 4);
        }
    }

    for (int kt = 0; kt < nk; kt++) {
        const int s = kt % 3;
        if (kt + 2 < nk) issue(kt + 2, (kt + 2) % 3);
        CP_COMMIT();
        CP_WAIT2();
        __syncthreads();

        const uint32_t sa = sbase + (uint32_t)s * STB;
        const uint32_t sb = sa + ABYTES;

#pragma unroll
        for (int ks = 0; ks < 4; ks++) {
            const uint32_t kx = (uint32_t)(2 * ks) << 4;
            unsigned af[MT][4], bf[NT][2];
#pragma unroll
            for (int i = 0; i < MT; i++)
                ldsm4(af[i][0], af[i][1], af[i][2], af[i][3], sa + (aaddr[i] ^ kx));
#pragma unroll
            for (int jp = 0; jp < NT / 2; jp++)
                ldsm4(bf[2 * jp][0], bf[2 * jp][1], bf[2 * jp + 1][0], bf[2 * jp + 1][1],
                      sb + (baddr[jp] ^ kx));
#pragma unroll
            for (int i = 0; i < MT; i++)
#pragma unroll
                for (int j = 0; j < NT; j++)
                    mma_f16(acc[i][j], af[i], bf[j]);
        }
        __syncthreads();
    }

    // ---- fused epilogue: stage 128x64 tile in fp32 smem ----
    float* tile = (float*)smc;               // [128][TP]
    float* rsum = tile + 128 * TP;           // [128]
#pragma unroll
    for (int i = 0; i < MT; i++) {
#pragma unroll
        for (int j = 0; j < NT; j++) {
            const int rl = wm * 32 + i * 16 + (lane >> 2);
            const int cl = wn * WNT + j * 8 + (lane & 3) * 2;
            *(float2*)&tile[rl * TP + cl]       = make_float2(acc[i][j][0], acc[i][j][1]);
            *(float2*)&tile[(rl + 8) * TP + cl] = make_float2(acc[i][j][2], acc[i][j][3]);
        }
    }
    __syncthreads();

    // softmax over modal axis (8 rows per batch) for each (batch, s)
    for (int p = tid; p < 16 * SEXT; p += 256) {
        const int bl = p >> 6, s = p & 63;
        float* col = &tile[(bl * 8) * TP + s];
        float mx = col[0];
#pragma unroll
        for (int m = 1; m < MODAL; m++) mx = fmaxf(mx, col[m * TP]);
        float sum = 0.f;
        float e[MODAL];
#pragma unroll
        for (int m = 0; m < MODAL; m++) { e[m] = expf(col[m * TP] - mx); sum += e[m]; }
        const float is = 1.f / sum;
#pragma unroll
        for (int m = 0; m < MODAL; m++) col[m * TP] = e[m] * is;
    }
    __syncthreads();

    // reciprocal row-sums over S
    for (int r = tid; r < 128; r += 256) {
        float t = 0.f;
        const float* row = &tile[r * TP];
#pragma unroll
        for (int s = 0; s < SEXT; s++) t += row[s];
        rsum[r] = 1.f / t;
    }
    __syncthreads();

    // emit fp16 a
    for (int idx = tid; idx < 128 * (SEXT / 2); idx += 256) {
        const int r = idx >> 5, sp = (idx & 31) * 2;
        const float rs = rsum[r];
        *(__half2*)&g_ah[(size_t)(bm + r) * SEXT + sp] =
            __floats2half2_rn(tile[r * TP + sp] * rs, tile[r * TP + sp + 1] * rs);
    }
}

// ---------------- attention pass A: scores + global min (fp16 inputs) ----------------
constexpr int QPAD = DMODEL + 4;

extern __shared__ float dynsmem[];

__global__ void __launch_bounds__(256) attn_scores_kernel() {
    float* qs = dynsmem;
    float* ks = dynsmem + MODAL * QPAD;
    const int b = blockIdx.x, tid = threadIdx.x;
    const uint4* qg = (const uint4*)(g_qph + (size_t)b * MODAL * DMODEL);
    const uint4* kg = (const uint4*)(g_kph + (size_t)b * MODAL * DMODEL);
    for (int i = tid; i < MODAL * DMODEL / 8; i += 256) {
        int m = i >> 7, c = i & 127;
        h8_to_f8(qg[i], &qs[m * QPAD + c * 8]);
        h8_to_f8(kg[i], &ks[m * QPAD + c * 8]);
    }
    __syncthreads();

    float lmin = 3.4e38f;
    for (int s = tid; s < NHEAD * MODAL * MODAL; s += 256) {
        int h = s >> 6, m = (s >> 3) & 7, n = s & 7;
        const float4* qr = (const float4*)&qs[m * QPAD + h * DK];
        const float4* kr = (const float4*)&ks[n * QPAD + h * DK];
        float acc = 0.f;
#pragma unroll
        for (int d = 0; d < 16; d++) {
            float4 a = qr[d], c = kr[d];
            acc += a.x * c.x + a.y * c.y + a.z * c.z + a.w * c.w;
        }
        acc *= 0.125f;
        g_scores[(size_t)b * 1024 + s] = acc;
        lmin = fminf(lmin, acc);
    }
#pragma unroll
    for (int o = 16; o; o >>= 1) lmin = fminf(lmin, __shfl_xor_sync(0xffffffffu, lmin, o));
    __shared__ float wmn[8];
    if ((tid & 31) == 0) wmn[tid >> 5] = lmin;
    __syncthreads();
    if (tid == 0) {
        float m = wmn[0];
#pragma unroll
        for (int i = 1; i < 8; i++) m = fminf(m, wmn[i]);
        atomicMin(&g_min_u, enc_min(m));
    }
}

// ---------------- attention pass B (fp16 v input, fp16 output) ----------------
__global__ void __launch_bounds__(256) attn_out_kernel() {
    __shared__ float vs[MODAL * QPAD];
    __shared__ float sc[NHEAD * 64];
    __shared__ float aw[NHEAD * 64];
    const int b = blockIdx.x, tid = threadIdx.x;
    const float inv = 1.f / fabsf(dec_min(g_min_u));

    const uint4* vg = (const uint4*)(g_vph + (size_t)b * MODAL * DMODEL);
    for (int i = tid; i < MODAL * DMODEL / 8; i += 256) {
        int m = i >> 7, c = i & 127;
        h8_to_f8(vg[i], &vs[m * QPAD + c * 8]);
    }
    for (int i = tid; i < 1024; i += 256)
        sc[i] = g_scores[(size_t)b * 1024 + i] * inv;
    __syncthreads();

    if (tid < 128) {
        int h = tid >> 3, m = tid & 7;
        float r[8]; float ss = 0.f;
#pragma unroll
        for (int n = 0; n < 8; n++) { r[n] = sc[h * 64 + m * 8 + n]; ss += r[n] * r[n]; }
        float nrm = fmaxf(sqrtf(ss), 1e-12f);
        float rn = 1.f / nrm;
        float mx = -3.4e38f;
#pragma unroll
        for (int n = 0; n < 8; n++) { r[n] *= rn; mx = fmaxf(mx, r[n]); }
        float sum = 0.f;
#pragma unroll
        for (int n = 0; n < 8; n++) { r[n] = expf(r[n] - mx); sum += r[n]; }
        float is = 1.f / sum;
#pragma unroll
        for (int n = 0; n < 8; n++) aw[h * 64 + m * 8 + n] = r[n] * is;
    }
    __syncthreads();

    __half* og = g_atth + (size_t)b * MODAL * DMODEL;
    for (int o = tid; o < MODAL * DMODEL; o += 256) {
        int m = o >> 10, col = o & 1023, h = col >> 6;
        float acc = 0.f;
#pragma unroll
        for (int n = 0; n < 8; n++) acc += aw[h * 64 + m * 8 + n] * vs[n * QPAD + col];
        og[o] = __float2half_rn(acc);
    }
}

// ---------------- LayerNorm: fp32 x in -> fp32 out + fp16 copy ----------------
__global__ void __launch_bounds__(256) ln_kernel(
    const float* __restrict__ gamma, const float* __restrict__ beta,
    float* __restrict__ out)
{
    const int wid = threadIdx.x >> 5, lane = threadIdx.x & 31;
    const size_t row = (size_t)blockIdx.x * 8 + wid;
    const float4* xr = (const float4*)(g_x + row * DMODEL);
    float4 v[8];
    float s = 0.f, s2 = 0.f;
#pragma unroll
    for (int i = 0; i < 8; i++) {
        v[i] = xr[lane + 32 * i];
        s += v[i].x + v[i].y + v[i].z + v[i].w;
        s2 += v[i].x * v[i].x + v[i].y * v[i].y + v[i].z * v[i].z + v[i].w * v[i].w;
    }
#pragma unroll
    for (int o = 16; o; o >>= 1) {
        s += __shfl_xor_sync(0xffffffffu, s, o);
        s2 += __shfl_xor_sync(0xffffffffu, s2, o);
    }
    const float mu = s * (1.f / DMODEL);
    const float var = fmaxf(s2 * (1.f / DMODEL) - mu * mu, 0.f);
    const float rs = rsqrtf(var + 1e-10f);
    float4* orow = (float4*)(out + row * DMODEL);
    __half2* hrow = (__half2*)(g_xh + row * DMODEL);
    const float4* gm = (const float4*)gamma;
    const float4* bt = (const float4*)beta;
#pragma unroll
    for (int i = 0; i < 8; i++) {
        int c4 = lane + 32 * i;
        float4 g = gm[c4], bb = bt[c4], x = v[i], r;
        r.x = (x.x - mu) * rs * g.x + bb.x;
        r.y = (x.y - mu) * rs * g.y + bb.y;
        r.z = (x.z - mu) * rs * g.z + bb.z;
        r.w = (x.w - mu) * rs * g.w + bb.w;
        orow[c4] = r;
        hrow[2 * c4]     = __float22half2_rn(make_float2(r.x, r.y));
        hrow[2 * c4 + 1] = __float22half2_rn(make_float2(r.z, r.w));
    }
}

// ---------------- launch ----------------
extern "C" void kernel_launch(void* const* d_in, const int* in_sizes, int n_in,
                              void* d_out, int out_size)
{
    const float* q     = (const float*)d_in[0];
    const float* k     = (const float*)d_in[1];
    const float* v     = (const float*)d_in[2];
    const float* Wq    = (const float*)d_in[3];
    const float* Wk    = (const float*)d_in[4];
    const float* Wv    = (const float*)d_in[5];
    const float* Wfc   = (const float*)d_in[6];
    const float* gamma = (const float*)d_in[7];
    const float* beta  = (const float*)d_in[8];
    const float* Wmk   = (const float*)d_in[9];
    const float* Wmv   = (const float*)d_in[10];
    float* out = (float*)d_out;

    float *px;
    __half *pqh, *pkh, *pvh, *pqph, *pkph, *pvph, *patth, *pxh, *pah;
    __half *pwqh, *pwkh, *pwvh, *pwfch, *pwmkh, *pwmvh;
    cudaGetSymbolAddress((void**)&px,    g_x);
    cudaGetSymbolAddress((void**)&pqh,   g_qh);
    cudaGetSymbolAddress((void**)&pkh,   g_kh);
    cudaGetSymbolAddress((void**)&pvh,   g_vh);
    cudaGetSymbolAddress((void**)&pqph,  g_qph);
    cudaGetSymbolAddress((void**)&pkph,  g_kph);
    cudaGetSymbolAddress((void**)&pvph,  g_vph);
    cudaGetSymbolAddress((void**)&patth, g_atth);
    cudaGetSymbolAddress((void**)&pxh,   g_xh);
    cudaGetSymbolAddress((void**)&pah,   g_ah);
    cudaGetSymbolAddress((void**)&pwqh,  g_wqh);
    cudaGetSymbolAddress((void**)&pwkh,  g_wkh);
    cudaGetSymbolAddress((void**)&pwvh,  g_wvh);
    cudaGetSymbolAddress((void**)&pwfch, g_wfch);
    cudaGetSymbolAddress((void**)&pwmkh, g_wmkh);
    cudaGetSymbolAddress((void**)&pwmvh, g_wmvh);

    const int smem_sc = 2 * MODAL * QPAD * (int)sizeof(float);
    cudaFuncSetAttribute(attn_scores_kernel,
                         cudaFuncAttributeMaxDynamicSharedMemorySize, smem_sc);

    const int smem128 = 3 * (128 * 128 + 128 * 128);  // 98304 B
    const int smem64  = 3 * (128 * 128 + 64 * 128);   // 73728 B
    cudaFuncSetAttribute(gemm_h<128, false, true>,
                         cudaFuncAttributeMaxDynamicSharedMemorySize, smem128);
    cudaFuncSetAttribute(gemm_h<128, true, false>,
                         cudaFuncAttributeMaxDynamicSharedMemorySize, smem128);
    cudaFuncSetAttribute(gemm_xa_ext,
                         cudaFuncAttributeMaxDynamicSharedMemorySize, smem64);

    init_min_kernel<<<1, 1>>>();

    // fp32 -> fp16 conversions (activations + weights)
    const int a4 = ROWS * DMODEL / 4;
    const int w4 = DMODEL * DMODEL / 4;
    const int s4 = SEXT * DMODEL / 4;
    cvt_h_kernel<<<(a4 + 255) / 256, 256>>>((const float4*)q,   (__half2*)pqh,   a4);
    cvt_h_kernel<<<(a4 + 255) / 256, 256>>>((const float4*)k,   (__half2*)pkh,   a4);
    cvt_h_kernel<<<(a4 + 255) / 256, 256>>>((const float4*)v,   (__half2*)pvh,   a4);
    cvt_h_kernel<<<(w4 + 255) / 256, 256>>>((const float4*)Wq,  (__half2*)pwqh,  w4);
    cvt_h_kernel<<<(w4 + 255) / 256, 256>>>((const float4*)Wk,  (__half2*)pwkh,  w4);
    cvt_h_kernel<<<(w4 + 255) / 256, 256>>>((const float4*)Wv,  (__half2*)pwvh,  w4);
    cvt_h_kernel<<<(w4 + 255) / 256, 256>>>((const float4*)Wfc, (__half2*)pwfch, w4);
    cvt_h_kernel<<<(s4 + 255) / 256, 256>>>((const float4*)Wmk, (__half2*)pwmkh, s4);
    cvt_h_kernel<<<(s4 + 255) / 256, 256>>>((const float4*)Wmv, (__half2*)pwmvh, s4);

    dim3 g1(DMODEL / 128, ROWS / 128);  // (8, 256)
    // projections -> fp16 outputs
    gemm_h<128, false, true><<<g1, 256, smem128>>>(pqh, pwqh, nullptr, pqph, DMODEL, DMODEL);
    gemm_h<128, false, true><<<g1, 256, smem128>>>(pkh, pwkh, nullptr, pkph, DMODEL, DMODEL);
    gemm_h<128, false, true><<<g1, 256, smem128>>>(pvh, pwvh, nullptr, pvph, DMODEL, DMODEL);

    attn_scores_kernel<<<BSZ, 256, smem_sc>>>();
    attn_out_kernel<<<BSZ, 256>>>();

    // x = attn_out @ Wfc^T + q (fp32 residual)
    gemm_h<128, true, false><<<g1, 256, smem128>>>(patth, pwfch, q, px, DMODEL, DMODEL);

    // LayerNorm -> out (fp32) + g_xh (fp16)
    ln_kernel<<<ROWS / 8, 256>>>(gamma, beta, out);

    // fused: xa = x @ Wmk^T, softmax over modal, renorm over S -> g_ah (fp16)
    gemm_xa_ext<<<dim3(1, ROWS / 128), 256, smem64>>>(pxh, pwmkh);

    // out = x + a @ Wmv^T (K=64, fp32 residual = out)
    gemm_h<128, true, false><<<dim3(DMODEL / 128, ROWS / 128), 256, smem128>>>(pah, pwmvh, out, out,
                                                                               SEXT, DMODEL);
}